// round 1
// baseline (speedup 1.0000x reference)
#include <cuda_runtime.h>
#include <math.h>

#define NUM_HEAD 16
#define D_MODEL 1024
#define HEAD_DIM 64
#define BATCH 2
#define SEQ 2048
#define MROWS (BATCH * SEQ)          // 4096
#define QKV_N (3 * D_MODEL)          // 3072

// Scratch (device globals: allocation-guard safe)
__device__ float g_qkv[(size_t)MROWS * QKV_N];    // [B,S,3*D] 48 MB
__device__ float g_attn[(size_t)MROWS * D_MODEL]; // [B,H,S,hd] contiguous = [4096,1024] row-major, 16 MB

// ---------------------------------------------------------------------------
// SGEMM: C[M,N] = A[M,K] @ B[K,N] + bias[N]
// 128x128 block tile, BK=8, 8x8 per thread, 256 threads.
// M,N divisible by 128; K divisible by 8 (holds for our shapes).
// ---------------------------------------------------------------------------
__global__ __launch_bounds__(256, 2)
void sgemm_bias(const float* __restrict__ A, const float* __restrict__ B,
                const float* __restrict__ bias, float* __restrict__ C,
                int M, int N, int K)
{
    const int BK = 8;
    __shared__ float As[BK][128];
    __shared__ float Bs[BK][128];

    int tid = threadIdx.x;
    int tx = tid & 15;          // 0..15  -> 8 cols each
    int ty = tid >> 4;          // 0..15  -> 8 rows each
    int row0 = blockIdx.y * 128;
    int col0 = blockIdx.x * 128;

    // A tile load: 128x8 floats = 256 float4, one per thread (store transposed)
    int a_r = tid >> 1;
    int a_c = (tid & 1) << 2;
    // B tile load: 8x128 floats = 256 float4, one per thread
    int b_r = tid >> 5;
    int b_c = (tid & 31) << 2;

    const float* Ap = A + (size_t)(row0 + a_r) * K + a_c;
    const float* Bp = B + (size_t)b_r * N + col0 + b_c;

    float acc[8][8];
    #pragma unroll
    for (int i = 0; i < 8; i++)
        #pragma unroll
        for (int j = 0; j < 8; j++) acc[i][j] = 0.f;

    for (int k0 = 0; k0 < K; k0 += BK) {
        float4 av = *(const float4*)(Ap + k0);
        float4 bv = *(const float4*)(Bp + (size_t)k0 * N);
        As[a_c + 0][a_r] = av.x;
        As[a_c + 1][a_r] = av.y;
        As[a_c + 2][a_r] = av.z;
        As[a_c + 3][a_r] = av.w;
        *(float4*)&Bs[b_r][b_c] = bv;
        __syncthreads();

        #pragma unroll
        for (int kk = 0; kk < BK; kk++) {
            float ar[8], br[8];
            *(float4*)&ar[0] = *(const float4*)&As[kk][ty * 8];
            *(float4*)&ar[4] = *(const float4*)&As[kk][ty * 8 + 4];
            *(float4*)&br[0] = *(const float4*)&Bs[kk][tx * 8];
            *(float4*)&br[4] = *(const float4*)&Bs[kk][tx * 8 + 4];
            #pragma unroll
            for (int i = 0; i < 8; i++)
                #pragma unroll
                for (int j = 0; j < 8; j++)
                    acc[i][j] = fmaf(ar[i], br[j], acc[i][j]);
        }
        __syncthreads();
    }

    #pragma unroll
    for (int i = 0; i < 8; i++) {
        int row = row0 + ty * 8 + i;
        #pragma unroll
        for (int j = 0; j < 8; j += 4) {
            int col = col0 + tx * 8 + j;
            float4 bb = *(const float4*)(bias + col);
            float4 v;
            v.x = acc[i][j + 0] + bb.x;
            v.y = acc[i][j + 1] + bb.y;
            v.z = acc[i][j + 2] + bb.z;
            v.w = acc[i][j + 3] + bb.w;
            *(float4*)(C + (size_t)row * N + col) = v;
        }
    }
}

// ---------------------------------------------------------------------------
// Flash attention (causal), fp32.
// Grid: (S/128, H, B). Block: 128 threads, thread t owns query row q0+t.
// Q (pre-scaled) and O accumulator live in registers; K/V 64-key tiles in smem,
// read with warp-uniform broadcast float4 (conflict-free).
// Output written to [B,H,S,hd] contiguous (reference's transpose-free reshape).
// ---------------------------------------------------------------------------
__global__ __launch_bounds__(128)
void flash_attn(const float* __restrict__ qkv, float* __restrict__ attn)
{
    const int QT = 128, KT = 64;
    __shared__ float Ks[KT][HEAD_DIM];
    __shared__ float Vs[KT][HEAD_DIM];

    int b = blockIdx.z;
    int h = blockIdx.y;
    int q0 = blockIdx.x * QT;
    int r = q0 + threadIdx.x;        // global query index in sequence

    const float scale = 0.125f;      // 1/sqrt(64)

    // Load this thread's Q row (fold in softmax scale)
    const float* qp = qkv + (size_t)(b * SEQ + r) * QKV_N + h * (3 * HEAD_DIM);
    float q[HEAD_DIM];
    #pragma unroll
    for (int d = 0; d < HEAD_DIM; d += 4) {
        float4 v = *(const float4*)(qp + d);
        q[d + 0] = v.x * scale;
        q[d + 1] = v.y * scale;
        q[d + 2] = v.z * scale;
        q[d + 3] = v.w * scale;
    }

    float o[HEAD_DIM];
    #pragma unroll
    for (int d = 0; d < HEAD_DIM; d++) o[d] = 0.f;
    float m = -1e30f, l = 0.f;

    int nkt = (q0 + QT) / KT;        // tiles covering keys [0, q0+127]
    for (int kt = 0; kt < nkt; kt++) {
        int k0 = kt * KT;
        __syncthreads();             // previous tile fully consumed
        // Cooperative K/V tile load: 64x64 each = 1024 float4 each, 8 per thread
        const float* kb = qkv + (size_t)(b * SEQ + k0) * QKV_N + h * (3 * HEAD_DIM) + HEAD_DIM;
        const float* vb = kb + HEAD_DIM;
        #pragma unroll
        for (int t = 0; t < 8; t++) {
            int i4 = threadIdx.x + t * 128;   // 0..1023
            int j = i4 >> 4;                  // 16 float4 per row
            int d = (i4 & 15) << 2;
            *(float4*)&Ks[j][d] = *(const float4*)(kb + (size_t)j * QKV_N + d);
            *(float4*)&Vs[j][d] = *(const float4*)(vb + (size_t)j * QKV_N + d);
        }
        __syncthreads();

        int jmax = r - k0 + 1;
        if (jmax > KT) jmax = KT;
        for (int j = 0; j < jmax; j++) {
            float s = 0.f;
            #pragma unroll
            for (int d = 0; d < HEAD_DIM; d += 4) {
                float4 kv = *(const float4*)&Ks[j][d];   // broadcast read
                s = fmaf(q[d + 0], kv.x, s);
                s = fmaf(q[d + 1], kv.y, s);
                s = fmaf(q[d + 2], kv.z, s);
                s = fmaf(q[d + 3], kv.w, s);
            }
            float p;
            if (s > m) {
                float c = __expf(m - s);     // m=-1e30 first time -> c=0
                l *= c;
                #pragma unroll
                for (int d = 0; d < HEAD_DIM; d++) o[d] *= c;
                m = s;
                p = 1.f;
            } else {
                p = __expf(s - m);
            }
            l += p;
            #pragma unroll
            for (int d = 0; d < HEAD_DIM; d += 4) {
                float4 vv = *(const float4*)&Vs[j][d];   // broadcast read
                o[d + 0] = fmaf(p, vv.x, o[d + 0]);
                o[d + 1] = fmaf(p, vv.y, o[d + 1]);
                o[d + 2] = fmaf(p, vv.z, o[d + 2]);
                o[d + 3] = fmaf(p, vv.w, o[d + 3]);
            }
        }
    }

    float inv = 1.f / l;
    float* op = attn + ((size_t)(b * NUM_HEAD + h) * SEQ + r) * HEAD_DIM;
    #pragma unroll
    for (int d = 0; d < HEAD_DIM; d += 4) {
        float4 v;
        v.x = o[d + 0] * inv;
        v.y = o[d + 1] * inv;
        v.z = o[d + 2] * inv;
        v.w = o[d + 3] * inv;
        *(float4*)(op + d) = v;
    }
}

// ---------------------------------------------------------------------------
extern "C" void kernel_launch(void* const* d_in, const int* in_sizes, int n_in,
                              void* d_out, int out_size)
{
    const float* x     = (const float*)d_in[0];  // [B,S,1024]
    const float* w_qkv = (const float*)d_in[1];  // [1024,3072]
    const float* b_qkv = (const float*)d_in[2];  // [3072]
    const float* w_out = (const float*)d_in[3];  // [1024,1024]
    const float* b_out = (const float*)d_in[4];  // [1024]
    float* out = (float*)d_out;                  // [B,S,1024]

    float* qkv;
    float* attn;
    cudaGetSymbolAddress((void**)&qkv, g_qkv);
    cudaGetSymbolAddress((void**)&attn, g_attn);

    // 1) QKV projection: [4096,1024] @ [1024,3072] + b
    dim3 g1(QKV_N / 128, MROWS / 128);
    sgemm_bias<<<g1, 256>>>(x, w_qkv, b_qkv, qkv, MROWS, QKV_N, D_MODEL);

    // 2) Causal flash attention -> [B,H,S,hd] contiguous
    dim3 g2(SEQ / 128, NUM_HEAD, BATCH);
    flash_attn<<<g2, 128>>>(qkv, attn);

    // 3) Output projection: [4096,1024] @ [1024,1024] + b
    dim3 g3(D_MODEL / 128, MROWS / 128);
    sgemm_bias<<<g3, 256>>>(attn, w_out, b_out, out, MROWS, D_MODEL, D_MODEL);
}

// round 2
// speedup vs baseline: 1.1133x; 1.1133x over previous
#include <cuda_runtime.h>
#include <math.h>

#define NUM_HEAD 16
#define D_MODEL 1024
#define HEAD_DIM 64
#define BATCH 2
#define SEQ 2048
#define MROWS (BATCH * SEQ)          // 4096
#define QKV_N (3 * D_MODEL)          // 3072

// Scratch (device globals: allocation-guard safe)
__device__ float g_qkv[(size_t)MROWS * QKV_N];    // [B,S,3*D] 48 MB
__device__ float g_attn[(size_t)MROWS * D_MODEL]; // [B,H,S,hd] contiguous = [4096,1024] row-major

// ---------------------------------------------------------------------------
// SGEMM: C[M,N] = A[M,K] @ B[K,N] + bias[N]
// 128x128 block tile, BK=8, 8x8 per thread, 256 threads.
// Global->register prefetch of next tile overlaps LDG latency with compute.
// ---------------------------------------------------------------------------
__global__ __launch_bounds__(256, 2)
void sgemm_bias(const float* __restrict__ A, const float* __restrict__ B,
                const float* __restrict__ bias, float* __restrict__ C,
                int M, int N, int K)
{
    const int BK = 8;
    __shared__ float As[BK][128];
    __shared__ float Bs[BK][128];

    int tid = threadIdx.x;
    int tx = tid & 15;          // 0..15  -> 8 cols each
    int ty = tid >> 4;          // 0..15  -> 8 rows each
    int row0 = blockIdx.y * 128;
    int col0 = blockIdx.x * 128;

    // A tile load: 128x8 floats = 256 float4, one per thread (store transposed)
    int a_r = tid >> 1;
    int a_c = (tid & 1) << 2;
    // B tile load: 8x128 floats = 256 float4, one per thread
    int b_r = tid >> 5;
    int b_c = (tid & 31) << 2;

    const float* Ap = A + (size_t)(row0 + a_r) * K + a_c;
    const float* Bp = B + (size_t)b_r * N + col0 + b_c;

    float acc[8][8];
    #pragma unroll
    for (int i = 0; i < 8; i++)
        #pragma unroll
        for (int j = 0; j < 8; j++) acc[i][j] = 0.f;

    // Prefetch first tile
    float4 av = *(const float4*)(Ap);
    float4 bv = *(const float4*)(Bp);

    for (int k0 = 0; k0 < K; k0 += BK) {
        As[a_c + 0][a_r] = av.x;
        As[a_c + 1][a_r] = av.y;
        As[a_c + 2][a_r] = av.z;
        As[a_c + 3][a_r] = av.w;
        *(float4*)&Bs[b_r][b_c] = bv;
        __syncthreads();

        // Prefetch next tile while computing current one
        if (k0 + BK < K) {
            av = *(const float4*)(Ap + k0 + BK);
            bv = *(const float4*)(Bp + (size_t)(k0 + BK) * N);
        }

        #pragma unroll
        for (int kk = 0; kk < BK; kk++) {
            float ar[8], br[8];
            *(float4*)&ar[0] = *(const float4*)&As[kk][ty * 8];
            *(float4*)&ar[4] = *(const float4*)&As[kk][ty * 8 + 4];
            *(float4*)&br[0] = *(const float4*)&Bs[kk][tx * 8];
            *(float4*)&br[4] = *(const float4*)&Bs[kk][tx * 8 + 4];
            #pragma unroll
            for (int i = 0; i < 8; i++)
                #pragma unroll
                for (int j = 0; j < 8; j++)
                    acc[i][j] = fmaf(ar[i], br[j], acc[i][j]);
        }
        __syncthreads();
    }

    #pragma unroll
    for (int i = 0; i < 8; i++) {
        int row = row0 + ty * 8 + i;
        #pragma unroll
        for (int j = 0; j < 8; j += 4) {
            int col = col0 + tx * 8 + j;
            float4 bb = *(const float4*)(bias + col);
            float4 v;
            v.x = acc[i][j + 0] + bb.x;
            v.y = acc[i][j + 1] + bb.y;
            v.z = acc[i][j + 2] + bb.z;
            v.w = acc[i][j + 3] + bb.w;
            *(float4*)(C + (size_t)row * N + col) = v;
        }
    }
}

// ---------------------------------------------------------------------------
// Flash attention (causal), fp32, ILP-restructured.
// Grid: (S/128, H, B). Block: 128 threads, thread t owns query row q0+t.
// Keys processed in PAIRS with 4 independent dot accumulators per key
// (8 FMA chains in flight) so the kernel is issue-bound, not latency-bound.
// Output written to [B,H,S,hd] contiguous (reference's transpose-free reshape).
// ---------------------------------------------------------------------------
__global__ __launch_bounds__(128)
void flash_attn(const float* __restrict__ qkv, float* __restrict__ attn)
{
    const int QT = 128, KT = 64;
    __shared__ float Ks[KT][HEAD_DIM];
    __shared__ float Vs[KT][HEAD_DIM];

    int b = blockIdx.z;
    int h = blockIdx.y;
    int q0 = blockIdx.x * QT;
    int r = q0 + threadIdx.x;        // global query index

    const float scale = 0.125f;      // 1/sqrt(64)

    const float* qp = qkv + (size_t)(b * SEQ + r) * QKV_N + h * (3 * HEAD_DIM);
    float q[HEAD_DIM];
    #pragma unroll
    for (int d = 0; d < HEAD_DIM; d += 4) {
        float4 v = *(const float4*)(qp + d);
        q[d + 0] = v.x * scale;
        q[d + 1] = v.y * scale;
        q[d + 2] = v.z * scale;
        q[d + 3] = v.w * scale;
    }

    float o[HEAD_DIM];
    #pragma unroll
    for (int d = 0; d < HEAD_DIM; d++) o[d] = 0.f;
    float m = -1e30f, l = 0.f;

    int nkt = (q0 + QT) / KT;
    for (int kt = 0; kt < nkt; kt++) {
        int k0 = kt * KT;
        __syncthreads();
        const float* kb = qkv + (size_t)(b * SEQ + k0) * QKV_N + h * (3 * HEAD_DIM) + HEAD_DIM;
        const float* vb = kb + HEAD_DIM;
        #pragma unroll
        for (int t = 0; t < 8; t++) {
            int i4 = threadIdx.x + t * 128;
            int j = i4 >> 4;
            int d = (i4 & 15) << 2;
            *(float4*)&Ks[j][d] = *(const float4*)(kb + (size_t)j * QKV_N + d);
            *(float4*)&Vs[j][d] = *(const float4*)(vb + (size_t)j * QKV_N + d);
        }
        __syncthreads();

        int jmax = r - k0 + 1;
        if (jmax > KT) jmax = KT;

        int j = 0;
        // ---- paired keys: 8 independent FMA chains ----
        for (; j + 2 <= jmax; j += 2) {
            float s0a = 0.f, s0b = 0.f, s0c = 0.f, s0d = 0.f;
            float s1a = 0.f, s1b = 0.f, s1c = 0.f, s1d = 0.f;
            #pragma unroll
            for (int d = 0; d < HEAD_DIM; d += 16) {
                float4 k0a = *(const float4*)&Ks[j][d];
                float4 k0b = *(const float4*)&Ks[j][d + 4];
                float4 k0c = *(const float4*)&Ks[j][d + 8];
                float4 k0d = *(const float4*)&Ks[j][d + 12];
                float4 k1a = *(const float4*)&Ks[j + 1][d];
                float4 k1b = *(const float4*)&Ks[j + 1][d + 4];
                float4 k1c = *(const float4*)&Ks[j + 1][d + 8];
                float4 k1d = *(const float4*)&Ks[j + 1][d + 12];
                s0a = fmaf(q[d+0], k0a.x, s0a); s0a = fmaf(q[d+1], k0a.y, s0a);
                s0a = fmaf(q[d+2], k0a.z, s0a); s0a = fmaf(q[d+3], k0a.w, s0a);
                s0b = fmaf(q[d+4], k0b.x, s0b); s0b = fmaf(q[d+5], k0b.y, s0b);
                s0b = fmaf(q[d+6], k0b.z, s0b); s0b = fmaf(q[d+7], k0b.w, s0b);
                s0c = fmaf(q[d+8], k0c.x, s0c); s0c = fmaf(q[d+9], k0c.y, s0c);
                s0c = fmaf(q[d+10], k0c.z, s0c); s0c = fmaf(q[d+11], k0c.w, s0c);
                s0d = fmaf(q[d+12], k0d.x, s0d); s0d = fmaf(q[d+13], k0d.y, s0d);
                s0d = fmaf(q[d+14], k0d.z, s0d); s0d = fmaf(q[d+15], k0d.w, s0d);
                s1a = fmaf(q[d+0], k1a.x, s1a); s1a = fmaf(q[d+1], k1a.y, s1a);
                s1a = fmaf(q[d+2], k1a.z, s1a); s1a = fmaf(q[d+3], k1a.w, s1a);
                s1b = fmaf(q[d+4], k1b.x, s1b); s1b = fmaf(q[d+5], k1b.y, s1b);
                s1b = fmaf(q[d+6], k1b.z, s1b); s1b = fmaf(q[d+7], k1b.w, s1b);
                s1c = fmaf(q[d+8], k1c.x, s1c); s1c = fmaf(q[d+9], k1c.y, s1c);
                s1c = fmaf(q[d+10], k1c.z, s1c); s1c = fmaf(q[d+11], k1c.w, s1c);
                s1d = fmaf(q[d+12], k1d.x, s1d); s1d = fmaf(q[d+13], k1d.y, s1d);
                s1d = fmaf(q[d+14], k1d.z, s1d); s1d = fmaf(q[d+15], k1d.w, s1d);
            }
            float s0 = (s0a + s0b) + (s0c + s0d);
            float s1 = (s1a + s1b) + (s1c + s1d);

            float p0, p1;
            if (s0 > m) {
                float c = __expf(m - s0);
                l *= c;
                #pragma unroll
                for (int d = 0; d < HEAD_DIM; d++) o[d] *= c;
                m = s0; p0 = 1.f;
            } else {
                p0 = __expf(s0 - m);
            }
            if (s1 > m) {
                float c = __expf(m - s1);
                l *= c; p0 *= c;
                #pragma unroll
                for (int d = 0; d < HEAD_DIM; d++) o[d] *= c;
                m = s1; p1 = 1.f;
            } else {
                p1 = __expf(s1 - m);
            }
            l += p0 + p1;

            #pragma unroll
            for (int d = 0; d < HEAD_DIM; d += 4) {
                float4 v0 = *(const float4*)&Vs[j][d];
                float4 v1 = *(const float4*)&Vs[j + 1][d];
                o[d+0] = fmaf(p1, v1.x, fmaf(p0, v0.x, o[d+0]));
                o[d+1] = fmaf(p1, v1.y, fmaf(p0, v0.y, o[d+1]));
                o[d+2] = fmaf(p1, v1.z, fmaf(p0, v0.z, o[d+2]));
                o[d+3] = fmaf(p1, v1.w, fmaf(p0, v0.w, o[d+3]));
            }
        }
        // ---- tail (at most one key) ----
        for (; j < jmax; j++) {
            float sa = 0.f, sb = 0.f, sc = 0.f, sd = 0.f;
            #pragma unroll
            for (int d = 0; d < HEAD_DIM; d += 16) {
                float4 ka = *(const float4*)&Ks[j][d];
                float4 kb2 = *(const float4*)&Ks[j][d + 4];
                float4 kc = *(const float4*)&Ks[j][d + 8];
                float4 kd = *(const float4*)&Ks[j][d + 12];
                sa = fmaf(q[d+0], ka.x, sa); sa = fmaf(q[d+1], ka.y, sa);
                sa = fmaf(q[d+2], ka.z, sa); sa = fmaf(q[d+3], ka.w, sa);
                sb = fmaf(q[d+4], kb2.x, sb); sb = fmaf(q[d+5], kb2.y, sb);
                sb = fmaf(q[d+6], kb2.z, sb); sb = fmaf(q[d+7], kb2.w, sb);
                sc = fmaf(q[d+8], kc.x, sc); sc = fmaf(q[d+9], kc.y, sc);
                sc = fmaf(q[d+10], kc.z, sc); sc = fmaf(q[d+11], kc.w, sc);
                sd = fmaf(q[d+12], kd.x, sd); sd = fmaf(q[d+13], kd.y, sd);
                sd = fmaf(q[d+14], kd.z, sd); sd = fmaf(q[d+15], kd.w, sd);
            }
            float s = (sa + sb) + (sc + sd);
            float p;
            if (s > m) {
                float c = __expf(m - s);
                l *= c;
                #pragma unroll
                for (int d = 0; d < HEAD_DIM; d++) o[d] *= c;
                m = s; p = 1.f;
            } else {
                p = __expf(s - m);
            }
            l += p;
            #pragma unroll
            for (int d = 0; d < HEAD_DIM; d += 4) {
                float4 vv = *(const float4*)&Vs[j][d];
                o[d+0] = fmaf(p, vv.x, o[d+0]);
                o[d+1] = fmaf(p, vv.y, o[d+1]);
                o[d+2] = fmaf(p, vv.z, o[d+2]);
                o[d+3] = fmaf(p, vv.w, o[d+3]);
            }
        }
    }

    float inv = 1.f / l;
    float* op = attn + ((size_t)(b * NUM_HEAD + h) * SEQ + r) * HEAD_DIM;
    #pragma unroll
    for (int d = 0; d < HEAD_DIM; d += 4) {
        float4 v;
        v.x = o[d + 0] * inv;
        v.y = o[d + 1] * inv;
        v.z = o[d + 2] * inv;
        v.w = o[d + 3] * inv;
        *(float4*)(op + d) = v;
    }
}

// ---------------------------------------------------------------------------
extern "C" void kernel_launch(void* const* d_in, const int* in_sizes, int n_in,
                              void* d_out, int out_size)
{
    const float* x     = (const float*)d_in[0];  // [B,S,1024]
    const float* w_qkv = (const float*)d_in[1];  // [1024,3072]
    const float* b_qkv = (const float*)d_in[2];  // [3072]
    const float* w_out = (const float*)d_in[3];  // [1024,1024]
    const float* b_out = (const float*)d_in[4];  // [1024]
    float* out = (float*)d_out;                  // [B,S,1024]

    float* qkv;
    float* attn;
    cudaGetSymbolAddress((void**)&qkv, g_qkv);
    cudaGetSymbolAddress((void**)&attn, g_attn);

    // 1) QKV projection: [4096,1024] @ [1024,3072] + b
    dim3 g1(QKV_N / 128, MROWS / 128);
    sgemm_bias<<<g1, 256>>>(x, w_qkv, b_qkv, qkv, MROWS, QKV_N, D_MODEL);

    // 2) Causal flash attention -> [B,H,S,hd] contiguous
    dim3 g2(SEQ / 128, NUM_HEAD, BATCH);
    flash_attn<<<g2, 128>>>(qkv, attn);

    // 3) Output projection: [4096,1024] @ [1024,1024] + b
    dim3 g3(D_MODEL / 128, MROWS / 128);
    sgemm_bias<<<g3, 256>>>(attn, w_out, b_out, out, MROWS, D_MODEL, D_MODEL);
}

// round 4
// speedup vs baseline: 1.4899x; 1.3382x over previous
#include <cuda_runtime.h>
#include <cuda_bf16.h>
#include <stdint.h>
#include <math.h>

#define NUM_HEAD 16
#define D_MODEL 1024
#define HEAD_DIM 64
#define BATCH 2
#define SEQ 2048
#define MROWS (BATCH * SEQ)          // 4096
#define QKV_N (3 * D_MODEL)          // 3072

// ---------------- scratch (device globals: allocation-guard safe) ----------
__device__ float g_qkv[(size_t)MROWS * QKV_N];    // [B,S,3*D] fp32
__device__ float g_attn[(size_t)MROWS * D_MODEL]; // [B,H,S,hd] contiguous

__device__ __nv_bfloat16 g_xhi[(size_t)MROWS * D_MODEL];
__device__ __nv_bfloat16 g_xlo[(size_t)MROWS * D_MODEL];
__device__ __nv_bfloat16 g_wqT_hi[(size_t)QKV_N * D_MODEL];   // [3072,1024] = w_qkv^T
__device__ __nv_bfloat16 g_wqT_lo[(size_t)QKV_N * D_MODEL];
__device__ __nv_bfloat16 g_woT_hi[(size_t)D_MODEL * D_MODEL]; // [1024,1024] = w_out^T
__device__ __nv_bfloat16 g_woT_lo[(size_t)D_MODEL * D_MODEL];
__device__ __nv_bfloat16 g_ahi[(size_t)MROWS * D_MODEL];
__device__ __nv_bfloat16 g_alo[(size_t)MROWS * D_MODEL];

// ---------------- PTX helpers (all plain-sm_103-portable) -------------------
__device__ __forceinline__ uint32_t smem_u32(const void* p) {
    uint32_t a;
    asm("{ .reg .u64 t; cvta.to.shared.u64 t, %1; cvt.u32.u64 %0, t; }" : "=r"(a) : "l"(p));
    return a;
}
__device__ __forceinline__ void cp16(uint32_t dst, const void* src) {
    asm volatile("cp.async.cg.shared.global [%0], [%1], 16;" :: "r"(dst), "l"(src) : "memory");
}
#define CP_COMMIT() asm volatile("cp.async.commit_group;" ::: "memory")
#define CP_WAIT(n)  asm volatile("cp.async.wait_group %0;" :: "n"(n) : "memory")

#define LDSM4(r0, r1, r2, r3, addr) \
    asm volatile("ldmatrix.sync.aligned.m8n8.x4.shared.b16 {%0,%1,%2,%3}, [%4];" \
                 : "=r"(r0), "=r"(r1), "=r"(r2), "=r"(r3) : "r"(addr))

#define MMA16816(d, a, b) \
    asm volatile("mma.sync.aligned.m16n8k16.row.col.f32.bf16.bf16.f32 " \
                 "{%0,%1,%2,%3},{%4,%5,%6,%7},{%8,%9},{%0,%1,%2,%3};" \
                 : "+f"((d)[0]), "+f"((d)[1]), "+f"((d)[2]), "+f"((d)[3]) \
                 : "r"((a)[0]), "r"((a)[1]), "r"((a)[2]), "r"((a)[3]), \
                   "r"((b)[0]), "r"((b)[1]))

// ---------------------------------------------------------------------------
// Elementwise fp32 -> (hi, lo) bf16 decomposition. n % 4 == 0.
// ---------------------------------------------------------------------------
__global__ void decomp_kernel(const float* __restrict__ in,
                              __nv_bfloat16* __restrict__ hi,
                              __nv_bfloat16* __restrict__ lo, int n)
{
    int i = (blockIdx.x * blockDim.x + threadIdx.x) * 4;
    if (i >= n) return;
    float4 v = *(const float4*)(in + i);
    __nv_bfloat16 hx = __float2bfloat16(v.x), hy = __float2bfloat16(v.y);
    __nv_bfloat16 hz = __float2bfloat16(v.z), hw = __float2bfloat16(v.w);
    __nv_bfloat162 h0; h0.x = hx; h0.y = hy;
    __nv_bfloat162 h1; h1.x = hz; h1.y = hw;
    __nv_bfloat162 l0, l1;
    l0.x = __float2bfloat16(v.x - __bfloat162float(hx));
    l0.y = __float2bfloat16(v.y - __bfloat162float(hy));
    l1.x = __float2bfloat16(v.z - __bfloat162float(hz));
    l1.y = __float2bfloat16(v.w - __bfloat162float(hw));
    *(__nv_bfloat162*)(hi + i) = h0;
    *(__nv_bfloat162*)(hi + i + 2) = h1;
    *(__nv_bfloat162*)(lo + i) = l0;
    *(__nv_bfloat162*)(lo + i + 2) = l1;
}

// ---------------------------------------------------------------------------
// Transposing decomposition: W[K,N] fp32 -> Wt_hi/lo[N,K] bf16. 32x32 tiles.
// ---------------------------------------------------------------------------
__global__ void transdecomp_kernel(const float* __restrict__ W,
                                   __nv_bfloat16* __restrict__ Thi,
                                   __nv_bfloat16* __restrict__ Tlo, int K, int N)
{
    __shared__ float tile[32][33];
    int n0 = blockIdx.x * 32, k0 = blockIdx.y * 32;
    #pragma unroll
    for (int i = 0; i < 4; i++)
        tile[threadIdx.y + i * 8][threadIdx.x] =
            W[(size_t)(k0 + threadIdx.y + i * 8) * N + n0 + threadIdx.x];
    __syncthreads();
    #pragma unroll
    for (int i = 0; i < 4; i++) {
        int n = n0 + threadIdx.y + i * 8;
        int k = k0 + threadIdx.x;
        float v = tile[threadIdx.x][threadIdx.y + i * 8];
        __nv_bfloat16 h = __float2bfloat16(v);
        Thi[(size_t)n * K + k] = h;
        Tlo[(size_t)n * K + k] = __float2bfloat16(v - __bfloat162float(h));
    }
}

// ---------------------------------------------------------------------------
// mma.sync bf16 hi/lo GEMM:  C[M,N] = A[M,K] @ B[N,K]^T + bias[N]  (fp32 out)
// 3-term error compensation: Ahi*Bhi + Alo*Bhi + Ahi*Blo.
// 128x128 CTA tile, BK=32, 8 warps (2m x 4n), warp tile 64x32.
// cp.async double-buffered smem; 80B row stride => conflict-free ldmatrix.
// ---------------------------------------------------------------------------
#define RS 80                 // smem row stride in bytes (32 bf16 + 8 pad)
#define TILE_B 10240          // 128 * RS
#define STAGE_B 40960         // 4 tiles
#define GEMM_SMEM 81920       // 2 stages

__global__ __launch_bounds__(256, 1)
void gemm_mma(const __nv_bfloat16* __restrict__ Ahi, const __nv_bfloat16* __restrict__ Alo,
              const __nv_bfloat16* __restrict__ Bhi, const __nv_bfloat16* __restrict__ Blo,
              const float* __restrict__ bias, float* __restrict__ C,
              int M, int N, int K)
{
    extern __shared__ char smem[];
    const uint32_t sb = smem_u32(smem);
    int tid = threadIdx.x;
    int lane = tid & 31, wid = tid >> 5;
    int wm = wid & 1, wn = wid >> 1;       // 2(m) x 4(n) warps
    int row0 = blockIdx.y * 128, col0 = blockIdx.x * 128;

    const __nv_bfloat16* Ah = Ahi + (size_t)row0 * K;
    const __nv_bfloat16* Al = Alo + (size_t)row0 * K;
    const __nv_bfloat16* Bh = Bhi + (size_t)col0 * K;
    const __nv_bfloat16* Bl = Blo + (size_t)col0 * K;

    float acc[4][4][4];
    #pragma unroll
    for (int i = 0; i < 4; i++)
        #pragma unroll
        for (int j = 0; j < 4; j++)
            #pragma unroll
            for (int r = 0; r < 4; r++) acc[i][j][r] = 0.f;

    // ldmatrix per-thread address components
    int m4 = lane >> 3, rin = lane & 7;
    int a_row = wm * 64 + ((m4 & 1) << 3) + rin;     // + mi*16
    int a_kc  = (m4 >> 1) << 3;                      // + ks*16 (bf16 cols)
    int b_row = wn * 32 + ((lane >> 4) << 3) + rin;  // + np*16
    int b_kc  = ((lane >> 3) & 1) << 3;

    // per-thread cp.async chunk coords (2 chunks per tile per thread)
    int r0c = tid >> 2, c0c = tid & 3;               // chunk tid
    int r1c = (tid + 256) >> 2, c1c = tid & 3;       // chunk tid+256

    const int NC = K / 32;

    // ---- stage loader (macro to keep cp.async in-line) ----
#define LOAD_STAGE(stg, kc) do {                                             \
        uint32_t base_ = sb + (stg) * STAGE_B;                               \
        uint32_t so0_ = (uint32_t)r0c * RS + c0c * 16;                       \
        uint32_t so1_ = (uint32_t)r1c * RS + c1c * 16;                       \
        size_t go0_ = (size_t)r0c * K + (kc) + c0c * 8;                      \
        size_t go1_ = (size_t)r1c * K + (kc) + c1c * 8;                      \
        cp16(base_ + so0_,               Ah + go0_);                         \
        cp16(base_ + so1_,               Ah + go1_);                         \
        cp16(base_ + TILE_B + so0_,      Al + go0_);                         \
        cp16(base_ + TILE_B + so1_,      Al + go1_);                         \
        cp16(base_ + 2 * TILE_B + so0_,  Bh + go0_);                         \
        cp16(base_ + 2 * TILE_B + so1_,  Bh + go1_);                         \
        cp16(base_ + 3 * TILE_B + so0_,  Bl + go0_);                         \
        cp16(base_ + 3 * TILE_B + so1_,  Bl + go1_);                         \
    } while (0)

    LOAD_STAGE(0, 0);
    CP_COMMIT();

    for (int c = 0; c < NC; c++) {
        int st = c & 1;
        if (c + 1 < NC) {
            LOAD_STAGE(st ^ 1, (c + 1) * 32);
            CP_COMMIT();
            CP_WAIT(1);
        } else {
            CP_WAIT(0);
        }
        __syncthreads();

        uint32_t aB = sb + st * STAGE_B;
        #pragma unroll
        for (int ks = 0; ks < 2; ks++) {
            uint32_t ah[4][4], al[4][4], bh[4][2], bl[4][2];
            #pragma unroll
            for (int mi = 0; mi < 4; mi++) {
                uint32_t ad = aB + (uint32_t)(a_row + mi * 16) * RS
                                 + (uint32_t)(ks * 16 + a_kc) * 2;
                LDSM4(ah[mi][0], ah[mi][1], ah[mi][2], ah[mi][3], ad);
                LDSM4(al[mi][0], al[mi][1], al[mi][2], al[mi][3], ad + TILE_B);
            }
            #pragma unroll
            for (int np = 0; np < 2; np++) {
                uint32_t bd = aB + 2 * TILE_B + (uint32_t)(b_row + np * 16) * RS
                                 + (uint32_t)(ks * 16 + b_kc) * 2;
                uint32_t t0, t1, t2, t3;
                LDSM4(t0, t1, t2, t3, bd);
                bh[np * 2][0] = t0; bh[np * 2][1] = t1;
                bh[np * 2 + 1][0] = t2; bh[np * 2 + 1][1] = t3;
                LDSM4(t0, t1, t2, t3, bd + TILE_B);
                bl[np * 2][0] = t0; bl[np * 2][1] = t1;
                bl[np * 2 + 1][0] = t2; bl[np * 2 + 1][1] = t3;
            }
            // pass-outer ordering: consecutive mmas never share an accumulator
            #pragma unroll
            for (int mi = 0; mi < 4; mi++)
                #pragma unroll
                for (int ni = 0; ni < 4; ni++)
                    MMA16816(acc[mi][ni], ah[mi], bh[ni]);
            #pragma unroll
            for (int mi = 0; mi < 4; mi++)
                #pragma unroll
                for (int ni = 0; ni < 4; ni++)
                    MMA16816(acc[mi][ni], al[mi], bh[ni]);
            #pragma unroll
            for (int mi = 0; mi < 4; mi++)
                #pragma unroll
                for (int ni = 0; ni < 4; ni++)
                    MMA16816(acc[mi][ni], ah[mi], bl[ni]);
        }
        __syncthreads();
    }
#undef LOAD_STAGE

    // epilogue: d0,d1 -> row g cols 2t,2t+1 ; d2,d3 -> row g+8
    int g = lane >> 2, tg = lane & 3;
    #pragma unroll
    for (int mi = 0; mi < 4; mi++) {
        int row = row0 + wm * 64 + mi * 16 + g;
        #pragma unroll
        for (int ni = 0; ni < 4; ni++) {
            int col = col0 + wn * 32 + ni * 8 + tg * 2;
            float2 bb = *(const float2*)(bias + col);
            float2 v0, v1;
            v0.x = acc[mi][ni][0] + bb.x;
            v0.y = acc[mi][ni][1] + bb.y;
            v1.x = acc[mi][ni][2] + bb.x;
            v1.y = acc[mi][ni][3] + bb.y;
            *(float2*)(C + (size_t)row * N + col) = v0;
            *(float2*)(C + (size_t)(row + 8) * N + col) = v1;
        }
    }
}

// ---------------------------------------------------------------------------
// Flash attention (causal), fp32, ILP-restructured (unchanged, known-passing).
// ---------------------------------------------------------------------------
__global__ __launch_bounds__(128)
void flash_attn(const float* __restrict__ qkv, float* __restrict__ attn)
{
    const int QT = 128, KT = 64;
    __shared__ float Ks[KT][HEAD_DIM];
    __shared__ float Vs[KT][HEAD_DIM];

    int b = blockIdx.z;
    int h = blockIdx.y;
    int q0 = blockIdx.x * QT;
    int r = q0 + threadIdx.x;

    const float scale = 0.125f;

    const float* qp = qkv + (size_t)(b * SEQ + r) * QKV_N + h * (3 * HEAD_DIM);
    float q[HEAD_DIM];
    #pragma unroll
    for (int d = 0; d < HEAD_DIM; d += 4) {
        float4 v = *(const float4*)(qp + d);
        q[d + 0] = v.x * scale;
        q[d + 1] = v.y * scale;
        q[d + 2] = v.z * scale;
        q[d + 3] = v.w * scale;
    }

    float o[HEAD_DIM];
    #pragma unroll
    for (int d = 0; d < HEAD_DIM; d++) o[d] = 0.f;
    float m = -1e30f, l = 0.f;

    int nkt = (q0 + QT) / KT;
    for (int kt = 0; kt < nkt; kt++) {
        int k0 = kt * KT;
        __syncthreads();
        const float* kb = qkv + (size_t)(b * SEQ + k0) * QKV_N + h * (3 * HEAD_DIM) + HEAD_DIM;
        const float* vb = kb + HEAD_DIM;
        #pragma unroll
        for (int t = 0; t < 8; t++) {
            int i4 = threadIdx.x + t * 128;
            int j = i4 >> 4;
            int d = (i4 & 15) << 2;
            *(float4*)&Ks[j][d] = *(const float4*)(kb + (size_t)j * QKV_N + d);
            *(float4*)&Vs[j][d] = *(const float4*)(vb + (size_t)j * QKV_N + d);
        }
        __syncthreads();

        int jmax = r - k0 + 1;
        if (jmax > KT) jmax = KT;

        int j = 0;
        for (; j + 2 <= jmax; j += 2) {
            float s0a = 0.f, s0b = 0.f, s0c = 0.f, s0d = 0.f;
            float s1a = 0.f, s1b = 0.f, s1c = 0.f, s1d = 0.f;
            #pragma unroll
            for (int d = 0; d < HEAD_DIM; d += 16) {
                float4 k0a = *(const float4*)&Ks[j][d];
                float4 k0b = *(const float4*)&Ks[j][d + 4];
                float4 k0c = *(const float4*)&Ks[j][d + 8];
                float4 k0d = *(const float4*)&Ks[j][d + 12];
                float4 k1a = *(const float4*)&Ks[j + 1][d];
                float4 k1b = *(const float4*)&Ks[j + 1][d + 4];
                float4 k1c = *(const float4*)&Ks[j + 1][d + 8];
                float4 k1d = *(const float4*)&Ks[j + 1][d + 12];
                s0a = fmaf(q[d+0], k0a.x, s0a); s0a = fmaf(q[d+1], k0a.y, s0a);
                s0a = fmaf(q[d+2], k0a.z, s0a); s0a = fmaf(q[d+3], k0a.w, s0a);
                s0b = fmaf(q[d+4], k0b.x, s0b); s0b = fmaf(q[d+5], k0b.y, s0b);
                s0b = fmaf(q[d+6], k0b.z, s0b); s0b = fmaf(q[d+7], k0b.w, s0b);
                s0c = fmaf(q[d+8], k0c.x, s0c); s0c = fmaf(q[d+9], k0c.y, s0c);
                s0c = fmaf(q[d+10], k0c.z, s0c); s0c = fmaf(q[d+11], k0c.w, s0c);
                s0d = fmaf(q[d+12], k0d.x, s0d); s0d = fmaf(q[d+13], k0d.y, s0d);
                s0d = fmaf(q[d+14], k0d.z, s0d); s0d = fmaf(q[d+15], k0d.w, s0d);
                s1a = fmaf(q[d+0], k1a.x, s1a); s1a = fmaf(q[d+1], k1a.y, s1a);
                s1a = fmaf(q[d+2], k1a.z, s1a); s1a = fmaf(q[d+3], k1a.w, s1a);
                s1b = fmaf(q[d+4], k1b.x, s1b); s1b = fmaf(q[d+5], k1b.y, s1b);
                s1b = fmaf(q[d+6], k1b.z, s1b); s1b = fmaf(q[d+7], k1b.w, s1b);
                s1c = fmaf(q[d+8], k1c.x, s1c); s1c = fmaf(q[d+9], k1c.y, s1c);
                s1c = fmaf(q[d+10], k1c.z, s1c); s1c = fmaf(q[d+11], k1c.w, s1c);
                s1d = fmaf(q[d+12], k1d.x, s1d); s1d = fmaf(q[d+13], k1d.y, s1d);
                s1d = fmaf(q[d+14], k1d.z, s1d); s1d = fmaf(q[d+15], k1d.w, s1d);
            }
            float s0 = (s0a + s0b) + (s0c + s0d);
            float s1 = (s1a + s1b) + (s1c + s1d);

            float p0, p1;
            if (s0 > m) {
                float c = __expf(m - s0);
                l *= c;
                #pragma unroll
                for (int d = 0; d < HEAD_DIM; d++) o[d] *= c;
                m = s0; p0 = 1.f;
            } else {
                p0 = __expf(s0 - m);
            }
            if (s1 > m) {
                float c = __expf(m - s1);
                l *= c; p0 *= c;
                #pragma unroll
                for (int d = 0; d < HEAD_DIM; d++) o[d] *= c;
                m = s1; p1 = 1.f;
            } else {
                p1 = __expf(s1 - m);
            }
            l += p0 + p1;

            #pragma unroll
            for (int d = 0; d < HEAD_DIM; d += 4) {
                float4 v0 = *(const float4*)&Vs[j][d];
                float4 v1 = *(const float4*)&Vs[j + 1][d];
                o[d+0] = fmaf(p1, v1.x, fmaf(p0, v0.x, o[d+0]));
                o[d+1] = fmaf(p1, v1.y, fmaf(p0, v0.y, o[d+1]));
                o[d+2] = fmaf(p1, v1.z, fmaf(p0, v0.z, o[d+2]));
                o[d+3] = fmaf(p1, v1.w, fmaf(p0, v0.w, o[d+3]));
            }
        }
        for (; j < jmax; j++) {
            float sa = 0.f, sb = 0.f, sc = 0.f, sd = 0.f;
            #pragma unroll
            for (int d = 0; d < HEAD_DIM; d += 16) {
                float4 ka = *(const float4*)&Ks[j][d];
                float4 kb2 = *(const float4*)&Ks[j][d + 4];
                float4 kc = *(const float4*)&Ks[j][d + 8];
                float4 kd = *(const float4*)&Ks[j][d + 12];
                sa = fmaf(q[d+0], ka.x, sa); sa = fmaf(q[d+1], ka.y, sa);
                sa = fmaf(q[d+2], ka.z, sa); sa = fmaf(q[d+3], ka.w, sa);
                sb = fmaf(q[d+4], kb2.x, sb); sb = fmaf(q[d+5], kb2.y, sb);
                sb = fmaf(q[d+6], kb2.z, sb); sb = fmaf(q[d+7], kb2.w, sb);
                sc = fmaf(q[d+8], kc.x, sc); sc = fmaf(q[d+9], kc.y, sc);
                sc = fmaf(q[d+10], kc.z, sc); sc = fmaf(q[d+11], kc.w, sc);
                sd = fmaf(q[d+12], kd.x, sd); sd = fmaf(q[d+13], kd.y, sd);
                sd = fmaf(q[d+14], kd.z, sd); sd = fmaf(q[d+15], kd.w, sd);
            }
            float s = (sa + sb) + (sc + sd);
            float p;
            if (s > m) {
                float c = __expf(m - s);
                l *= c;
                #pragma unroll
                for (int d = 0; d < HEAD_DIM; d++) o[d] *= c;
                m = s; p = 1.f;
            } else {
                p = __expf(s - m);
            }
            l += p;
            #pragma unroll
            for (int d = 0; d < HEAD_DIM; d += 4) {
                float4 vv = *(const float4*)&Vs[j][d];
                o[d+0] = fmaf(p, vv.x, o[d+0]);
                o[d+1] = fmaf(p, vv.y, o[d+1]);
                o[d+2] = fmaf(p, vv.z, o[d+2]);
                o[d+3] = fmaf(p, vv.w, o[d+3]);
            }
        }
    }

    float inv = 1.f / l;
    float* op = attn + ((size_t)(b * NUM_HEAD + h) * SEQ + r) * HEAD_DIM;
    #pragma unroll
    for (int d = 0; d < HEAD_DIM; d += 4) {
        float4 v;
        v.x = o[d + 0] * inv;
        v.y = o[d + 1] * inv;
        v.z = o[d + 2] * inv;
        v.w = o[d + 3] * inv;
        *(float4*)(op + d) = v;
    }
}

// ---------------------------------------------------------------------------
extern "C" void kernel_launch(void* const* d_in, const int* in_sizes, int n_in,
                              void* d_out, int out_size)
{
    const float* x     = (const float*)d_in[0];
    const float* w_qkv = (const float*)d_in[1];
    const float* b_qkv = (const float*)d_in[2];
    const float* w_out = (const float*)d_in[3];
    const float* b_out = (const float*)d_in[4];
    float* out = (float*)d_out;

    float *qkv, *attn;
    __nv_bfloat16 *xhi, *xlo, *wqhi, *wqlo, *wohi, *wolo, *ahi, *alo;
    cudaGetSymbolAddress((void**)&qkv, g_qkv);
    cudaGetSymbolAddress((void**)&attn, g_attn);
    cudaGetSymbolAddress((void**)&xhi, g_xhi);
    cudaGetSymbolAddress((void**)&xlo, g_xlo);
    cudaGetSymbolAddress((void**)&wqhi, g_wqT_hi);
    cudaGetSymbolAddress((void**)&wqlo, g_wqT_lo);
    cudaGetSymbolAddress((void**)&wohi, g_woT_hi);
    cudaGetSymbolAddress((void**)&wolo, g_woT_lo);
    cudaGetSymbolAddress((void**)&ahi, g_ahi);
    cudaGetSymbolAddress((void**)&alo, g_alo);

    cudaFuncSetAttribute(gemm_mma, cudaFuncAttributeMaxDynamicSharedMemorySize, GEMM_SMEM);

    // 0) decompose inputs
    {
        int n = MROWS * D_MODEL;
        decomp_kernel<<<n / 1024, 256>>>(x, xhi, xlo, n);
    }
    transdecomp_kernel<<<dim3(QKV_N / 32, D_MODEL / 32), dim3(32, 8)>>>(w_qkv, wqhi, wqlo, D_MODEL, QKV_N);
    transdecomp_kernel<<<dim3(D_MODEL / 32, D_MODEL / 32), dim3(32, 8)>>>(w_out, wohi, wolo, D_MODEL, D_MODEL);

    // 1) QKV projection (tensor core mma.sync)
    gemm_mma<<<dim3(QKV_N / 128, MROWS / 128), 256, GEMM_SMEM>>>(
        xhi, xlo, wqhi, wqlo, b_qkv, qkv, MROWS, QKV_N, D_MODEL);

    // 2) causal flash attention -> [B,H,S,hd] contiguous
    flash_attn<<<dim3(SEQ / 128, NUM_HEAD, BATCH), 128>>>(qkv, attn);

    // 3) decompose attention output, then output projection (tensor core)
    {
        int n = MROWS * D_MODEL;
        decomp_kernel<<<n / 1024, 256>>>(attn, ahi, alo, n);
    }
    gemm_mma<<<dim3(D_MODEL / 128, MROWS / 128), 256, GEMM_SMEM>>>(
        ahi, alo, wohi, wolo, b_out, out, MROWS, D_MODEL, D_MODEL);
}

// round 5
// speedup vs baseline: 3.3429x; 2.2437x over previous
#include <cuda_runtime.h>
#include <cuda_bf16.h>
#include <stdint.h>
#include <math.h>

#define NUM_HEAD 16
#define D_MODEL 1024
#define HEAD_DIM 64
#define BATCH 2
#define SEQ 2048
#define MROWS (BATCH * SEQ)          // 4096
#define QKV_N (3 * D_MODEL)          // 3072

// ---------------- scratch (device globals: allocation-guard safe) ----------
__device__ __nv_bfloat16 g_qkvhi[(size_t)MROWS * QKV_N];      // [B,S,3*D] hi
__device__ __nv_bfloat16 g_qkvlo[(size_t)MROWS * QKV_N];      // lo
__device__ __nv_bfloat16 g_xhi[(size_t)MROWS * D_MODEL];
__device__ __nv_bfloat16 g_xlo[(size_t)MROWS * D_MODEL];
__device__ __nv_bfloat16 g_wqT_hi[(size_t)QKV_N * D_MODEL];
__device__ __nv_bfloat16 g_wqT_lo[(size_t)QKV_N * D_MODEL];
__device__ __nv_bfloat16 g_woT_hi[(size_t)D_MODEL * D_MODEL];
__device__ __nv_bfloat16 g_woT_lo[(size_t)D_MODEL * D_MODEL];
__device__ __nv_bfloat16 g_ahi[(size_t)MROWS * D_MODEL];      // attn out hi [B,H,S,hd]
__device__ __nv_bfloat16 g_alo[(size_t)MROWS * D_MODEL];

// ---------------- PTX helpers ----------------------------------------------
__device__ __forceinline__ uint32_t smem_u32(const void* p) {
    uint32_t a;
    asm("{ .reg .u64 t; cvta.to.shared.u64 t, %1; cvt.u32.u64 %0, t; }" : "=r"(a) : "l"(p));
    return a;
}
__device__ __forceinline__ void cp16(uint32_t dst, const void* src) {
    asm volatile("cp.async.cg.shared.global [%0], [%1], 16;" :: "r"(dst), "l"(src) : "memory");
}
#define CP_COMMIT() asm volatile("cp.async.commit_group;" ::: "memory")
#define CP_WAIT(n)  asm volatile("cp.async.wait_group %0;" :: "n"(n) : "memory")

#define LDSM4(r0, r1, r2, r3, addr) \
    asm volatile("ldmatrix.sync.aligned.m8n8.x4.shared.b16 {%0,%1,%2,%3}, [%4];" \
                 : "=r"(r0), "=r"(r1), "=r"(r2), "=r"(r3) : "r"(addr))
#define LDSM4T(r0, r1, r2, r3, addr) \
    asm volatile("ldmatrix.sync.aligned.m8n8.x4.trans.shared.b16 {%0,%1,%2,%3}, [%4];" \
                 : "=r"(r0), "=r"(r1), "=r"(r2), "=r"(r3) : "r"(addr))

#define MMA16816(d, a, b) \
    asm volatile("mma.sync.aligned.m16n8k16.row.col.f32.bf16.bf16.f32 " \
                 "{%0,%1,%2,%3},{%4,%5,%6,%7},{%8,%9},{%0,%1,%2,%3};" \
                 : "+f"((d)[0]), "+f"((d)[1]), "+f"((d)[2]), "+f"((d)[3]) \
                 : "r"((a)[0]), "r"((a)[1]), "r"((a)[2]), "r"((a)[3]), \
                   "r"((b)[0]), "r"((b)[1]))

// pack two fp32 into bf16x2 hi, produce bf16x2 lo (residual)
__device__ __forceinline__ uint32_t packpair(float x, float y, uint32_t& lo) {
    __nv_bfloat16 hx = __float2bfloat16(x), hy = __float2bfloat16(y);
    __nv_bfloat162 h; h.x = hx; h.y = hy;
    __nv_bfloat162 l;
    l.x = __float2bfloat16(x - __bfloat162float(hx));
    l.y = __float2bfloat16(y - __bfloat162float(hy));
    lo = *(uint32_t*)&l;
    return *(uint32_t*)&h;
}

// ---------------------------------------------------------------------------
// Elementwise fp32 -> (hi, lo) bf16 decomposition.
// ---------------------------------------------------------------------------
__global__ void decomp_kernel(const float* __restrict__ in,
                              __nv_bfloat16* __restrict__ hi,
                              __nv_bfloat16* __restrict__ lo, int n)
{
    int i = (blockIdx.x * blockDim.x + threadIdx.x) * 4;
    if (i >= n) return;
    float4 v = *(const float4*)(in + i);
    uint32_t l0, l1;
    uint32_t h0 = packpair(v.x, v.y, l0);
    uint32_t h1 = packpair(v.z, v.w, l1);
    *(uint32_t*)(hi + i) = h0; *(uint32_t*)(hi + i + 2) = h1;
    *(uint32_t*)(lo + i) = l0; *(uint32_t*)(lo + i + 2) = l1;
}

// ---------------------------------------------------------------------------
// Transposing decomposition: W[K,N] fp32 -> Wt_hi/lo[N,K] bf16.
// ---------------------------------------------------------------------------
__global__ void transdecomp_kernel(const float* __restrict__ W,
                                   __nv_bfloat16* __restrict__ Thi,
                                   __nv_bfloat16* __restrict__ Tlo, int K, int N)
{
    __shared__ float tile[32][33];
    int n0 = blockIdx.x * 32, k0 = blockIdx.y * 32;
    #pragma unroll
    for (int i = 0; i < 4; i++)
        tile[threadIdx.y + i * 8][threadIdx.x] =
            W[(size_t)(k0 + threadIdx.y + i * 8) * N + n0 + threadIdx.x];
    __syncthreads();
    #pragma unroll
    for (int i = 0; i < 4; i++) {
        int n = n0 + threadIdx.y + i * 8;
        int k = k0 + threadIdx.x;
        float v = tile[threadIdx.x][threadIdx.y + i * 8];
        __nv_bfloat16 h = __float2bfloat16(v);
        Thi[(size_t)n * K + k] = h;
        Tlo[(size_t)n * K + k] = __float2bfloat16(v - __bfloat162float(h));
    }
}

// ---------------------------------------------------------------------------
// mma.sync bf16 hi/lo GEMM:  C = A[M,K] @ B[N,K]^T + bias (3-term compensation)
// If Chi != null, writes hi/lo bf16 decomposition instead of fp32 C.
// ---------------------------------------------------------------------------
#define RS 80
#define TILE_B 10240
#define STAGE_B 40960
#define GEMM_SMEM 81920

__global__ __launch_bounds__(256, 1)
void gemm_mma(const __nv_bfloat16* __restrict__ Ahi, const __nv_bfloat16* __restrict__ Alo,
              const __nv_bfloat16* __restrict__ Bhi, const __nv_bfloat16* __restrict__ Blo,
              const float* __restrict__ bias, float* __restrict__ C,
              __nv_bfloat16* __restrict__ Chi, __nv_bfloat16* __restrict__ Clo,
              int M, int N, int K)
{
    extern __shared__ char smem[];
    const uint32_t sb = smem_u32(smem);
    int tid = threadIdx.x;
    int lane = tid & 31, wid = tid >> 5;
    int wm = wid & 1, wn = wid >> 1;
    int row0 = blockIdx.y * 128, col0 = blockIdx.x * 128;

    const __nv_bfloat16* Ah = Ahi + (size_t)row0 * K;
    const __nv_bfloat16* Al = Alo + (size_t)row0 * K;
    const __nv_bfloat16* Bh = Bhi + (size_t)col0 * K;
    const __nv_bfloat16* Bl = Blo + (size_t)col0 * K;

    float acc[4][4][4];
    #pragma unroll
    for (int i = 0; i < 4; i++)
        #pragma unroll
        for (int j = 0; j < 4; j++)
            #pragma unroll
            for (int r = 0; r < 4; r++) acc[i][j][r] = 0.f;

    int m4 = lane >> 3, rin = lane & 7;
    int a_row = wm * 64 + ((m4 & 1) << 3) + rin;
    int a_kc  = (m4 >> 1) << 3;
    int b_row = wn * 32 + ((lane >> 4) << 3) + rin;
    int b_kc  = ((lane >> 3) & 1) << 3;

    int r0c = tid >> 2, c0c = tid & 3;
    int r1c = (tid + 256) >> 2, c1c = tid & 3;

    const int NC = K / 32;

#define LOAD_STAGE(stg, kc) do {                                             \
        uint32_t base_ = sb + (stg) * STAGE_B;                               \
        uint32_t so0_ = (uint32_t)r0c * RS + c0c * 16;                       \
        uint32_t so1_ = (uint32_t)r1c * RS + c1c * 16;                       \
        size_t go0_ = (size_t)r0c * K + (kc) + c0c * 8;                      \
        size_t go1_ = (size_t)r1c * K + (kc) + c1c * 8;                      \
        cp16(base_ + so0_,               Ah + go0_);                         \
        cp16(base_ + so1_,               Ah + go1_);                         \
        cp16(base_ + TILE_B + so0_,      Al + go0_);                         \
        cp16(base_ + TILE_B + so1_,      Al + go1_);                         \
        cp16(base_ + 2 * TILE_B + so0_,  Bh + go0_);                         \
        cp16(base_ + 2 * TILE_B + so1_,  Bh + go1_);                         \
        cp16(base_ + 3 * TILE_B + so0_,  Bl + go0_);                         \
        cp16(base_ + 3 * TILE_B + so1_,  Bl + go1_);                         \
    } while (0)

    LOAD_STAGE(0, 0);
    CP_COMMIT();

    for (int c = 0; c < NC; c++) {
        int st = c & 1;
        if (c + 1 < NC) {
            LOAD_STAGE(st ^ 1, (c + 1) * 32);
            CP_COMMIT();
            CP_WAIT(1);
        } else {
            CP_WAIT(0);
        }
        __syncthreads();

        uint32_t aB = sb + st * STAGE_B;
        #pragma unroll
        for (int ks = 0; ks < 2; ks++) {
            uint32_t ah[4][4], al[4][4], bh[4][2], bl[4][2];
            #pragma unroll
            for (int mi = 0; mi < 4; mi++) {
                uint32_t ad = aB + (uint32_t)(a_row + mi * 16) * RS
                                 + (uint32_t)(ks * 16 + a_kc) * 2;
                LDSM4(ah[mi][0], ah[mi][1], ah[mi][2], ah[mi][3], ad);
                LDSM4(al[mi][0], al[mi][1], al[mi][2], al[mi][3], ad + TILE_B);
            }
            #pragma unroll
            for (int np = 0; np < 2; np++) {
                uint32_t bd = aB + 2 * TILE_B + (uint32_t)(b_row + np * 16) * RS
                                 + (uint32_t)(ks * 16 + b_kc) * 2;
                uint32_t t0, t1, t2, t3;
                LDSM4(t0, t1, t2, t3, bd);
                bh[np * 2][0] = t0; bh[np * 2][1] = t1;
                bh[np * 2 + 1][0] = t2; bh[np * 2 + 1][1] = t3;
                LDSM4(t0, t1, t2, t3, bd + TILE_B);
                bl[np * 2][0] = t0; bl[np * 2][1] = t1;
                bl[np * 2 + 1][0] = t2; bl[np * 2 + 1][1] = t3;
            }
            #pragma unroll
            for (int mi = 0; mi < 4; mi++)
                #pragma unroll
                for (int ni = 0; ni < 4; ni++)
                    MMA16816(acc[mi][ni], ah[mi], bh[ni]);
            #pragma unroll
            for (int mi = 0; mi < 4; mi++)
                #pragma unroll
                for (int ni = 0; ni < 4; ni++)
                    MMA16816(acc[mi][ni], al[mi], bh[ni]);
            #pragma unroll
            for (int mi = 0; mi < 4; mi++)
                #pragma unroll
                for (int ni = 0; ni < 4; ni++)
                    MMA16816(acc[mi][ni], ah[mi], bl[ni]);
        }
        __syncthreads();
    }
#undef LOAD_STAGE

    int g = lane >> 2, tg = lane & 3;
    #pragma unroll
    for (int mi = 0; mi < 4; mi++) {
        int row = row0 + wm * 64 + mi * 16 + g;
        #pragma unroll
        for (int ni = 0; ni < 4; ni++) {
            int col = col0 + wn * 32 + ni * 8 + tg * 2;
            float2 bb = *(const float2*)(bias + col);
            float v0x = acc[mi][ni][0] + bb.x, v0y = acc[mi][ni][1] + bb.y;
            float v1x = acc[mi][ni][2] + bb.x, v1y = acc[mi][ni][3] + bb.y;
            if (Chi) {
                uint32_t lo0, lo1;
                uint32_t hi0 = packpair(v0x, v0y, lo0);
                uint32_t hi1 = packpair(v1x, v1y, lo1);
                *(uint32_t*)(Chi + (size_t)row * N + col) = hi0;
                *(uint32_t*)(Clo + (size_t)row * N + col) = lo0;
                *(uint32_t*)(Chi + (size_t)(row + 8) * N + col) = hi1;
                *(uint32_t*)(Clo + (size_t)(row + 8) * N + col) = lo1;
            } else {
                float2 v0; v0.x = v0x; v0.y = v0y;
                float2 v1; v1.x = v1x; v1.y = v1y;
                *(float2*)(C + (size_t)row * N + col) = v0;
                *(float2*)(C + (size_t)(row + 8) * N + col) = v1;
            }
        }
    }
}

// ---------------------------------------------------------------------------
// Flash attention (causal) on mma.sync bf16 with hi/lo compensation.
// Br=128 (8 warps x 16 rows), Bc=64. K/V hi/lo tiles double-buffered via
// cp.async. S = 0.125*(QhiKhi + QloKhi + QhiKlo); softmax fp32 in registers;
// O += PhiVhi + PloVhi + PhiVlo (V via ldmatrix.trans, no transpose needed).
// Writes hi/lo bf16 output directly ([B,H,S,hd] contiguous).
// ---------------------------------------------------------------------------
#define RS2 144               // 64 bf16 = 128B rows + 16B pad
#define TILE_KV 9216          // 64 * 144
#define STAGE_KV 36864        // Khi,Klo,Vhi,Vlo
#define QOFF 73728            // after 2 KV stages
#define ATT_SMEM 110592

__global__ __launch_bounds__(256, 1)
void flash_attn_mma(const __nv_bfloat16* __restrict__ qkvhi,
                    const __nv_bfloat16* __restrict__ qkvlo,
                    __nv_bfloat16* __restrict__ ahi,
                    __nv_bfloat16* __restrict__ alo)
{
    extern __shared__ char smem[];
    const uint32_t sb = smem_u32(smem);
    int tid = threadIdx.x, lane = tid & 31, w = tid >> 5;
    int h = blockIdx.y, b = blockIdx.z;
    int q0 = (int)(gridDim.x - 1 - blockIdx.x) * 128;   // heavy CTAs first

    const __nv_bfloat16* qh_g = qkvhi + (size_t)b * SEQ * QKV_N + h * 192;
    const __nv_bfloat16* ql_g = qkvlo + (size_t)b * SEQ * QKV_N + h * 192;
    const __nv_bfloat16* kvsrc[4] = {qh_g + 64, ql_g + 64, qh_g + 128, ql_g + 128};

    // ---- issue Q load (group 0) ----
    #pragma unroll
    for (int i = 0; i < 8; i++) {
        int part = i >> 2;
        int rem = tid + 256 * (i & 3);
        int rw = rem >> 3, cc = rem & 7;
        const __nv_bfloat16* src = (part ? ql_g : qh_g) + (size_t)(q0 + rw) * QKV_N + cc * 8;
        cp16(sb + QOFF + part * 18432 + (uint32_t)rw * RS2 + cc * 16, src);
    }
    CP_COMMIT();

#define LOAD_KV(stg, kk) do {                                                  \
        _Pragma("unroll")                                                      \
        for (int i_ = 0; i_ < 8; i_++) {                                       \
            int sub_ = i_ >> 1;                                                \
            int rem_ = tid + 256 * (i_ & 1);                                   \
            int rw_ = rem_ >> 3, cc_ = rem_ & 7;                               \
            const __nv_bfloat16* src_ =                                        \
                kvsrc[sub_] + (size_t)((kk) + rw_) * QKV_N + cc_ * 8;          \
            cp16(sb + (stg) * STAGE_KV + sub_ * TILE_KV +                      \
                 (uint32_t)rw_ * RS2 + cc_ * 16, src_);                        \
        } } while (0)

    LOAD_KV(0, 0);          // group 1
    CP_COMMIT();
    CP_WAIT(1);             // Q ready
    __syncthreads();

    // ---- extract Q fragments (kept in registers) ----
    uint32_t qhf[4][4], qlf[4][4];
    {
        int ar = 16 * w + (((lane >> 3) & 1) << 3) + (lane & 7);
        int akc = (lane >> 4) << 3;
        #pragma unroll
        for (int ks = 0; ks < 4; ks++) {
            uint32_t ad = sb + QOFF + (uint32_t)ar * RS2 + (uint32_t)(ks * 16 + akc) * 2;
            LDSM4(qhf[ks][0], qhf[ks][1], qhf[ks][2], qhf[ks][3], ad);
            LDSM4(qlf[ks][0], qlf[ks][1], qlf[ks][2], qlf[ks][3], ad + 18432);
        }
    }

    int g = lane >> 2, tg = lane & 3;
    int qr0 = q0 + 16 * w + g, qr1 = qr0 + 8;
    int qmax = q0 + 16 * w + 15;

    float o[8][4];
    #pragma unroll
    for (int nt = 0; nt < 8; nt++)
        #pragma unroll
        for (int i = 0; i < 4; i++) o[nt][i] = 0.f;
    float m0 = -1e30f, m1 = -1e30f, l0 = 0.f, l1 = 0.f;

    int ntile = q0 / 64 + 2;
    int krow = (((lane >> 4)) << 3) + (lane & 7);   // B-frag row base (non-trans)
    int kkc  = ((lane >> 3) & 1) << 3;
    int vrow_b = (((lane >> 3) & 1) << 3) + (lane & 7);  // trans row base
    int vcol_b = (lane >> 4) << 3;

    for (int t = 0; t < ntile; t++) {
        int k0 = t * 64;
        int buf = t & 1;
        if (t + 1 < ntile) {
            LOAD_KV(buf ^ 1, (t + 1) * 64);
            CP_COMMIT();
            CP_WAIT(1);
        } else {
            CP_WAIT(0);
        }
        __syncthreads();

        if (k0 <= qmax) {                       // warp has unmasked rows here
            uint32_t kb = sb + buf * STAGE_KV;
            float s[8][4];
            #pragma unroll
            for (int nt = 0; nt < 8; nt++)
                #pragma unroll
                for (int i = 0; i < 4; i++) s[nt][i] = 0.f;

            // ---- S = Q K^T (3 passes) ----
            #pragma unroll
            for (int ks = 0; ks < 4; ks++) {
                uint32_t khf[8][2], klf[8][2];
                #pragma unroll
                for (int n16 = 0; n16 < 4; n16++) {
                    uint32_t ad = kb + (uint32_t)(n16 * 16 + krow) * RS2
                                     + (uint32_t)(ks * 16 + kkc) * 2;
                    uint32_t t0, t1, t2, t3;
                    LDSM4(t0, t1, t2, t3, ad);
                    khf[n16 * 2][0] = t0; khf[n16 * 2][1] = t1;
                    khf[n16 * 2 + 1][0] = t2; khf[n16 * 2 + 1][1] = t3;
                    LDSM4(t0, t1, t2, t3, ad + TILE_KV);
                    klf[n16 * 2][0] = t0; klf[n16 * 2][1] = t1;
                    klf[n16 * 2 + 1][0] = t2; klf[n16 * 2 + 1][1] = t3;
                }
                #pragma unroll
                for (int nt = 0; nt < 8; nt++) MMA16816(s[nt], qhf[ks], khf[nt]);
                #pragma unroll
                for (int nt = 0; nt < 8; nt++) MMA16816(s[nt], qlf[ks], khf[nt]);
                #pragma unroll
                for (int nt = 0; nt < 8; nt++) MMA16816(s[nt], qhf[ks], klf[nt]);
            }

            // ---- scale + causal mask ----
            #pragma unroll
            for (int nt = 0; nt < 8; nt++)
                #pragma unroll
                for (int i = 0; i < 4; i++) s[nt][i] *= 0.125f;
            if (k0 + 63 > q0 + 16 * w) {
                #pragma unroll
                for (int nt = 0; nt < 8; nt++) {
                    int c = k0 + nt * 8 + 2 * tg;
                    if (c     > qr0) s[nt][0] = -1e30f;
                    if (c + 1 > qr0) s[nt][1] = -1e30f;
                    if (c     > qr1) s[nt][2] = -1e30f;
                    if (c + 1 > qr1) s[nt][3] = -1e30f;
                }
            }

            // ---- online softmax ----
            float rm0 = -1e30f, rm1 = -1e30f;
            #pragma unroll
            for (int nt = 0; nt < 8; nt++) {
                rm0 = fmaxf(rm0, fmaxf(s[nt][0], s[nt][1]));
                rm1 = fmaxf(rm1, fmaxf(s[nt][2], s[nt][3]));
            }
            rm0 = fmaxf(rm0, __shfl_xor_sync(0xffffffffu, rm0, 1));
            rm0 = fmaxf(rm0, __shfl_xor_sync(0xffffffffu, rm0, 2));
            rm1 = fmaxf(rm1, __shfl_xor_sync(0xffffffffu, rm1, 1));
            rm1 = fmaxf(rm1, __shfl_xor_sync(0xffffffffu, rm1, 2));
            float mn0 = fmaxf(m0, rm0), mn1 = fmaxf(m1, rm1);
            float al0 = __expf(m0 - mn0), al1 = __expf(m1 - mn1);
            m0 = mn0; m1 = mn1;
            float rs0 = 0.f, rs1 = 0.f;
            #pragma unroll
            for (int nt = 0; nt < 8; nt++) {
                s[nt][0] = __expf(s[nt][0] - mn0);
                s[nt][1] = __expf(s[nt][1] - mn0);
                s[nt][2] = __expf(s[nt][2] - mn1);
                s[nt][3] = __expf(s[nt][3] - mn1);
                rs0 += s[nt][0] + s[nt][1];
                rs1 += s[nt][2] + s[nt][3];
            }
            rs0 += __shfl_xor_sync(0xffffffffu, rs0, 1);
            rs0 += __shfl_xor_sync(0xffffffffu, rs0, 2);
            rs1 += __shfl_xor_sync(0xffffffffu, rs1, 1);
            rs1 += __shfl_xor_sync(0xffffffffu, rs1, 2);
            l0 = l0 * al0 + rs0;
            l1 = l1 * al1 + rs1;
            #pragma unroll
            for (int nt = 0; nt < 8; nt++) {
                o[nt][0] *= al0; o[nt][1] *= al0;
                o[nt][2] *= al1; o[nt][3] *= al1;
            }

            // ---- pack P (accumulator frag -> A frag), hi/lo ----
            uint32_t phi[4][4], plo[4][4];
            #pragma unroll
            for (int ks = 0; ks < 4; ks++) {
                phi[ks][0] = packpair(s[2 * ks][0],     s[2 * ks][1],     plo[ks][0]);
                phi[ks][1] = packpair(s[2 * ks][2],     s[2 * ks][3],     plo[ks][1]);
                phi[ks][2] = packpair(s[2 * ks + 1][0], s[2 * ks + 1][1], plo[ks][2]);
                phi[ks][3] = packpair(s[2 * ks + 1][2], s[2 * ks + 1][3], plo[ks][3]);
            }

            // ---- O += P V (3 passes), V via ldmatrix.trans ----
            uint32_t vb = kb + 2 * TILE_KV;
            #pragma unroll
            for (int ks = 0; ks < 4; ks++) {
                uint32_t vhf[8][2], vlf[8][2];
                #pragma unroll
                for (int n16 = 0; n16 < 4; n16++) {
                    uint32_t ad = vb + (uint32_t)(ks * 16 + vrow_b) * RS2
                                     + (uint32_t)(n16 * 16 + vcol_b) * 2;
                    uint32_t t0, t1, t2, t3;
                    LDSM4T(t0, t1, t2, t3, ad);
                    vhf[n16 * 2][0] = t0; vhf[n16 * 2][1] = t1;
                    vhf[n16 * 2 + 1][0] = t2; vhf[n16 * 2 + 1][1] = t3;
                    LDSM4T(t0, t1, t2, t3, ad + TILE_KV);
                    vlf[n16 * 2][0] = t0; vlf[n16 * 2][1] = t1;
                    vlf[n16 * 2 + 1][0] = t2; vlf[n16 * 2 + 1][1] = t3;
                }
                #pragma unroll
                for (int nt = 0; nt < 8; nt++) MMA16816(o[nt], phi[ks], vhf[nt]);
                #pragma unroll
                for (int nt = 0; nt < 8; nt++) MMA16816(o[nt], plo[ks], vhf[nt]);
                #pragma unroll
                for (int nt = 0; nt < 8; nt++) MMA16816(o[nt], phi[ks], vlf[nt]);
            }
        }
        __syncthreads();
    }
#undef LOAD_KV

    // ---- epilogue: normalize, write hi/lo bf16 ([B,H,S,hd] contiguous) ----
    float inv0 = 1.f / l0, inv1 = 1.f / l1;
    size_t base0 = ((size_t)(b * NUM_HEAD + h) * SEQ + qr0) * HEAD_DIM;
    size_t base1 = ((size_t)(b * NUM_HEAD + h) * SEQ + qr1) * HEAD_DIM;
    #pragma unroll
    for (int nt = 0; nt < 8; nt++) {
        int col = nt * 8 + 2 * tg;
        uint32_t lo0, lo1;
        uint32_t hi0 = packpair(o[nt][0] * inv0, o[nt][1] * inv0, lo0);
        uint32_t hi1 = packpair(o[nt][2] * inv1, o[nt][3] * inv1, lo1);
        *(uint32_t*)(ahi + base0 + col) = hi0;
        *(uint32_t*)(alo + base0 + col) = lo0;
        *(uint32_t*)(ahi + base1 + col) = hi1;
        *(uint32_t*)(alo + base1 + col) = lo1;
    }
}

// ---------------------------------------------------------------------------
extern "C" void kernel_launch(void* const* d_in, const int* in_sizes, int n_in,
                              void* d_out, int out_size)
{
    const float* x     = (const float*)d_in[0];
    const float* w_qkv = (const float*)d_in[1];
    const float* b_qkv = (const float*)d_in[2];
    const float* w_out = (const float*)d_in[3];
    const float* b_out = (const float*)d_in[4];
    float* out = (float*)d_out;

    __nv_bfloat16 *qkvhi, *qkvlo, *xhi, *xlo, *wqhi, *wqlo, *wohi, *wolo, *ahi, *alo;
    cudaGetSymbolAddress((void**)&qkvhi, g_qkvhi);
    cudaGetSymbolAddress((void**)&qkvlo, g_qkvlo);
    cudaGetSymbolAddress((void**)&xhi, g_xhi);
    cudaGetSymbolAddress((void**)&xlo, g_xlo);
    cudaGetSymbolAddress((void**)&wqhi, g_wqT_hi);
    cudaGetSymbolAddress((void**)&wqlo, g_wqT_lo);
    cudaGetSymbolAddress((void**)&wohi, g_woT_hi);
    cudaGetSymbolAddress((void**)&wolo, g_woT_lo);
    cudaGetSymbolAddress((void**)&ahi, g_ahi);
    cudaGetSymbolAddress((void**)&alo, g_alo);

    cudaFuncSetAttribute(gemm_mma, cudaFuncAttributeMaxDynamicSharedMemorySize, GEMM_SMEM);
    cudaFuncSetAttribute(flash_attn_mma, cudaFuncAttributeMaxDynamicSharedMemorySize, ATT_SMEM);

    // 0) decompose x and weights
    decomp_kernel<<<MROWS * D_MODEL / 1024, 256>>>(x, xhi, xlo, MROWS * D_MODEL);
    transdecomp_kernel<<<dim3(QKV_N / 32, D_MODEL / 32), dim3(32, 8)>>>(w_qkv, wqhi, wqlo, D_MODEL, QKV_N);
    transdecomp_kernel<<<dim3(D_MODEL / 32, D_MODEL / 32), dim3(32, 8)>>>(w_out, wohi, wolo, D_MODEL, D_MODEL);

    // 1) QKV projection -> hi/lo bf16 directly
    gemm_mma<<<dim3(QKV_N / 128, MROWS / 128), 256, GEMM_SMEM>>>(
        xhi, xlo, wqhi, wqlo, b_qkv, nullptr, qkvhi, qkvlo, MROWS, QKV_N, D_MODEL);

    // 2) causal flash attention (tensor cores) -> ahi/alo
    flash_attn_mma<<<dim3(SEQ / 128, NUM_HEAD, BATCH), 256, ATT_SMEM>>>(
        qkvhi, qkvlo, ahi, alo);

    // 3) output projection -> fp32 out
    gemm_mma<<<dim3(D_MODEL / 128, MROWS / 128), 256, GEMM_SMEM>>>(
        ahi, alo, wohi, wolo, b_out, out, nullptr, nullptr, MROWS, D_MODEL, D_MODEL);
}

// round 6
// speedup vs baseline: 3.6895x; 1.1037x over previous
#include <cuda_runtime.h>
#include <cuda_bf16.h>
#include <stdint.h>
#include <math.h>

#define NUM_HEAD 16
#define D_MODEL 1024
#define HEAD_DIM 64
#define BATCH 2
#define SEQ 2048
#define MROWS (BATCH * SEQ)          // 4096
#define QKV_N (3 * D_MODEL)          // 3072

// ---------------- scratch (device globals: allocation-guard safe) ----------
__device__ __nv_bfloat16 g_qkvhi[(size_t)MROWS * QKV_N];      // [B,S,3*D] hi
__device__ __nv_bfloat16 g_qkvlo[(size_t)MROWS * QKV_N];      // lo
__device__ __nv_bfloat16 g_xhi[(size_t)MROWS * D_MODEL];
__device__ __nv_bfloat16 g_xlo[(size_t)MROWS * D_MODEL];
__device__ __nv_bfloat16 g_wqT_hi[(size_t)QKV_N * D_MODEL];
__device__ __nv_bfloat16 g_wqT_lo[(size_t)QKV_N * D_MODEL];
__device__ __nv_bfloat16 g_woT_hi[(size_t)D_MODEL * D_MODEL];
__device__ __nv_bfloat16 g_woT_lo[(size_t)D_MODEL * D_MODEL];
__device__ __nv_bfloat16 g_ahi[(size_t)MROWS * D_MODEL];      // attn out hi [B,H,S,hd]
__device__ __nv_bfloat16 g_alo[(size_t)MROWS * D_MODEL];

// ---------------- PTX helpers ----------------------------------------------
__device__ __forceinline__ uint32_t smem_u32(const void* p) {
    uint32_t a;
    asm("{ .reg .u64 t; cvta.to.shared.u64 t, %1; cvt.u32.u64 %0, t; }" : "=r"(a) : "l"(p));
    return a;
}
__device__ __forceinline__ void cp16(uint32_t dst, const void* src) {
    asm volatile("cp.async.cg.shared.global [%0], [%1], 16;" :: "r"(dst), "l"(src) : "memory");
}
#define CP_COMMIT() asm volatile("cp.async.commit_group;" ::: "memory")
#define CP_WAIT(n)  asm volatile("cp.async.wait_group %0;" :: "n"(n) : "memory")

#define LDSM4(r0, r1, r2, r3, addr) \
    asm volatile("ldmatrix.sync.aligned.m8n8.x4.shared.b16 {%0,%1,%2,%3}, [%4];" \
                 : "=r"(r0), "=r"(r1), "=r"(r2), "=r"(r3) : "r"(addr))
#define LDSM4T(r0, r1, r2, r3, addr) \
    asm volatile("ldmatrix.sync.aligned.m8n8.x4.trans.shared.b16 {%0,%1,%2,%3}, [%4];" \
                 : "=r"(r0), "=r"(r1), "=r"(r2), "=r"(r3) : "r"(addr))

#define MMA16816(d, a, b) \
    asm volatile("mma.sync.aligned.m16n8k16.row.col.f32.bf16.bf16.f32 " \
                 "{%0,%1,%2,%3},{%4,%5,%6,%7},{%8,%9},{%0,%1,%2,%3};" \
                 : "+f"((d)[0]), "+f"((d)[1]), "+f"((d)[2]), "+f"((d)[3]) \
                 : "r"((a)[0]), "r"((a)[1]), "r"((a)[2]), "r"((a)[3]), \
                   "r"((b)[0]), "r"((b)[1]))

// pack two fp32 into bf16x2 hi, produce bf16x2 lo (residual)
__device__ __forceinline__ uint32_t packpair(float x, float y, uint32_t& lo) {
    __nv_bfloat16 hx = __float2bfloat16(x), hy = __float2bfloat16(y);
    __nv_bfloat162 h; h.x = hx; h.y = hy;
    __nv_bfloat162 l;
    l.x = __float2bfloat16(x - __bfloat162float(hx));
    l.y = __float2bfloat16(y - __bfloat162float(hy));
    lo = *(uint32_t*)&l;
    return *(uint32_t*)&h;
}

// ---------------------------------------------------------------------------
// Elementwise fp32 -> (hi, lo) bf16 decomposition.
// ---------------------------------------------------------------------------
__global__ void decomp_kernel(const float* __restrict__ in,
                              __nv_bfloat16* __restrict__ hi,
                              __nv_bfloat16* __restrict__ lo, int n)
{
    int i = (blockIdx.x * blockDim.x + threadIdx.x) * 4;
    if (i >= n) return;
    float4 v = *(const float4*)(in + i);
    uint32_t l0, l1;
    uint32_t h0 = packpair(v.x, v.y, l0);
    uint32_t h1 = packpair(v.z, v.w, l1);
    *(uint32_t*)(hi + i) = h0; *(uint32_t*)(hi + i + 2) = h1;
    *(uint32_t*)(lo + i) = l0; *(uint32_t*)(lo + i + 2) = l1;
}

// ---------------------------------------------------------------------------
// Transposing decomposition: W[K,N] fp32 -> Wt_hi/lo[N,K] bf16.
// ---------------------------------------------------------------------------
__global__ void transdecomp_kernel(const float* __restrict__ W,
                                   __nv_bfloat16* __restrict__ Thi,
                                   __nv_bfloat16* __restrict__ Tlo, int K, int N)
{
    __shared__ float tile[32][33];
    int n0 = blockIdx.x * 32, k0 = blockIdx.y * 32;
    #pragma unroll
    for (int i = 0; i < 4; i++)
        tile[threadIdx.y + i * 8][threadIdx.x] =
            W[(size_t)(k0 + threadIdx.y + i * 8) * N + n0 + threadIdx.x];
    __syncthreads();
    #pragma unroll
    for (int i = 0; i < 4; i++) {
        int n = n0 + threadIdx.y + i * 8;
        int k = k0 + threadIdx.x;
        float v = tile[threadIdx.x][threadIdx.y + i * 8];
        __nv_bfloat16 h = __float2bfloat16(v);
        Thi[(size_t)n * K + k] = h;
        Tlo[(size_t)n * K + k] = __float2bfloat16(v - __bfloat162float(h));
    }
}

// ---------------------------------------------------------------------------
// mma.sync bf16 hi/lo GEMM:  C = A[M,K] @ B[N,K]^T + bias (3-term compensation)
// If Chi != null, writes hi/lo bf16 decomposition instead of fp32 C.
// Pass-split inner loop keeps live fragments at 24 regs -> <=128 total
// -> 2 CTAs/SM so barrier/load phases of one CTA overlap MMA of the other.
// ---------------------------------------------------------------------------
#define RS 80
#define TILE_B 10240
#define STAGE_B 40960
#define GEMM_SMEM 81920

__global__ __launch_bounds__(256, 2)
void gemm_mma(const __nv_bfloat16* __restrict__ Ahi, const __nv_bfloat16* __restrict__ Alo,
              const __nv_bfloat16* __restrict__ Bhi, const __nv_bfloat16* __restrict__ Blo,
              const float* __restrict__ bias, float* __restrict__ C,
              __nv_bfloat16* __restrict__ Chi, __nv_bfloat16* __restrict__ Clo,
              int M, int N, int K)
{
    extern __shared__ char smem[];
    const uint32_t sb = smem_u32(smem);
    int tid = threadIdx.x;
    int lane = tid & 31, wid = tid >> 5;
    int wm = wid & 1, wn = wid >> 1;
    int row0 = blockIdx.y * 128, col0 = blockIdx.x * 128;

    const __nv_bfloat16* Ah = Ahi + (size_t)row0 * K;
    const __nv_bfloat16* Al = Alo + (size_t)row0 * K;
    const __nv_bfloat16* Bh = Bhi + (size_t)col0 * K;
    const __nv_bfloat16* Bl = Blo + (size_t)col0 * K;

    float acc[4][4][4];
    #pragma unroll
    for (int i = 0; i < 4; i++)
        #pragma unroll
        for (int j = 0; j < 4; j++)
            #pragma unroll
            for (int r = 0; r < 4; r++) acc[i][j][r] = 0.f;

    int m4 = lane >> 3, rin = lane & 7;
    int a_row = wm * 64 + ((m4 & 1) << 3) + rin;
    int a_kc  = (m4 >> 1) << 3;
    int b_row = wn * 32 + ((lane >> 4) << 3) + rin;
    int b_kc  = ((lane >> 3) & 1) << 3;

    int r0c = tid >> 2, c0c = tid & 3;
    int r1c = (tid + 256) >> 2, c1c = tid & 3;

    const int NC = K / 32;

#define LOAD_STAGE(stg, kc) do {                                             \
        uint32_t base_ = sb + (stg) * STAGE_B;                               \
        uint32_t so0_ = (uint32_t)r0c * RS + c0c * 16;                       \
        uint32_t so1_ = (uint32_t)r1c * RS + c1c * 16;                       \
        size_t go0_ = (size_t)r0c * K + (kc) + c0c * 8;                      \
        size_t go1_ = (size_t)r1c * K + (kc) + c1c * 8;                      \
        cp16(base_ + so0_,               Ah + go0_);                         \
        cp16(base_ + so1_,               Ah + go1_);                         \
        cp16(base_ + TILE_B + so0_,      Al + go0_);                         \
        cp16(base_ + TILE_B + so1_,      Al + go1_);                         \
        cp16(base_ + 2 * TILE_B + so0_,  Bh + go0_);                         \
        cp16(base_ + 2 * TILE_B + so1_,  Bh + go1_);                         \
        cp16(base_ + 3 * TILE_B + so0_,  Bl + go0_);                         \
        cp16(base_ + 3 * TILE_B + so1_,  Bl + go1_);                         \
    } while (0)

    LOAD_STAGE(0, 0);
    CP_COMMIT();

    for (int c = 0; c < NC; c++) {
        int st = c & 1;
        if (c + 1 < NC) {
            LOAD_STAGE(st ^ 1, (c + 1) * 32);
            CP_COMMIT();
            CP_WAIT(1);
        } else {
            CP_WAIT(0);
        }
        __syncthreads();

        uint32_t aB = sb + st * STAGE_B;
        #pragma unroll
        for (int ks = 0; ks < 2; ks++) {
            uint32_t af[4][4], bf[4][2];
            uint32_t adh[4];
            #pragma unroll
            for (int mi = 0; mi < 4; mi++)
                adh[mi] = aB + (uint32_t)(a_row + mi * 16) * RS
                             + (uint32_t)(ks * 16 + a_kc) * 2;
            uint32_t bdh = aB + 2 * TILE_B + (uint32_t)b_row * RS
                             + (uint32_t)(ks * 16 + b_kc) * 2;

            // ---- pass 0: Ahi * Bhi ----
            #pragma unroll
            for (int mi = 0; mi < 4; mi++)
                LDSM4(af[mi][0], af[mi][1], af[mi][2], af[mi][3], adh[mi]);
            #pragma unroll
            for (int np = 0; np < 2; np++) {
                uint32_t t0, t1, t2, t3;
                LDSM4(t0, t1, t2, t3, bdh + (uint32_t)(np * 16) * RS);
                bf[np * 2][0] = t0; bf[np * 2][1] = t1;
                bf[np * 2 + 1][0] = t2; bf[np * 2 + 1][1] = t3;
            }
            #pragma unroll
            for (int mi = 0; mi < 4; mi++)
                #pragma unroll
                for (int ni = 0; ni < 4; ni++)
                    MMA16816(acc[mi][ni], af[mi], bf[ni]);

            // ---- pass 1: Alo * Bhi (reuse bf) ----
            #pragma unroll
            for (int mi = 0; mi < 4; mi++)
                LDSM4(af[mi][0], af[mi][1], af[mi][2], af[mi][3], adh[mi] + TILE_B);
            #pragma unroll
            for (int mi = 0; mi < 4; mi++)
                #pragma unroll
                for (int ni = 0; ni < 4; ni++)
                    MMA16816(acc[mi][ni], af[mi], bf[ni]);

            // ---- pass 2: Ahi * Blo ----
            #pragma unroll
            for (int mi = 0; mi < 4; mi++)
                LDSM4(af[mi][0], af[mi][1], af[mi][2], af[mi][3], adh[mi]);
            #pragma unroll
            for (int np = 0; np < 2; np++) {
                uint32_t t0, t1, t2, t3;
                LDSM4(t0, t1, t2, t3, bdh + TILE_B + (uint32_t)(np * 16) * RS);
                bf[np * 2][0] = t0; bf[np * 2][1] = t1;
                bf[np * 2 + 1][0] = t2; bf[np * 2 + 1][1] = t3;
            }
            #pragma unroll
            for (int mi = 0; mi < 4; mi++)
                #pragma unroll
                for (int ni = 0; ni < 4; ni++)
                    MMA16816(acc[mi][ni], af[mi], bf[ni]);
        }
        __syncthreads();
    }
#undef LOAD_STAGE

    int g = lane >> 2, tg = lane & 3;
    #pragma unroll
    for (int mi = 0; mi < 4; mi++) {
        int row = row0 + wm * 64 + mi * 16 + g;
        #pragma unroll
        for (int ni = 0; ni < 4; ni++) {
            int col = col0 + wn * 32 + ni * 8 + tg * 2;
            float2 bb = *(const float2*)(bias + col);
            float v0x = acc[mi][ni][0] + bb.x, v0y = acc[mi][ni][1] + bb.y;
            float v1x = acc[mi][ni][2] + bb.x, v1y = acc[mi][ni][3] + bb.y;
            if (Chi) {
                uint32_t lo0, lo1;
                uint32_t hi0 = packpair(v0x, v0y, lo0);
                uint32_t hi1 = packpair(v1x, v1y, lo1);
                *(uint32_t*)(Chi + (size_t)row * N + col) = hi0;
                *(uint32_t*)(Clo + (size_t)row * N + col) = lo0;
                *(uint32_t*)(Chi + (size_t)(row + 8) * N + col) = hi1;
                *(uint32_t*)(Clo + (size_t)(row + 8) * N + col) = lo1;
            } else {
                float2 v0; v0.x = v0x; v0.y = v0y;
                float2 v1; v1.x = v1x; v1.y = v1y;
                *(float2*)(C + (size_t)row * N + col) = v0;
                *(float2*)(C + (size_t)(row + 8) * N + col) = v1;
            }
        }
    }
}

// ---------------------------------------------------------------------------
// Flash attention (causal) on mma.sync bf16 with hi/lo compensation.
// (unchanged from R5 — known-passing)
// ---------------------------------------------------------------------------
#define RS2 144
#define TILE_KV 9216
#define STAGE_KV 36864
#define QOFF 73728
#define ATT_SMEM 110592

__global__ __launch_bounds__(256, 1)
void flash_attn_mma(const __nv_bfloat16* __restrict__ qkvhi,
                    const __nv_bfloat16* __restrict__ qkvlo,
                    __nv_bfloat16* __restrict__ ahi,
                    __nv_bfloat16* __restrict__ alo)
{
    extern __shared__ char smem[];
    const uint32_t sb = smem_u32(smem);
    int tid = threadIdx.x, lane = tid & 31, w = tid >> 5;
    int h = blockIdx.y, b = blockIdx.z;
    int q0 = (int)(gridDim.x - 1 - blockIdx.x) * 128;

    const __nv_bfloat16* qh_g = qkvhi + (size_t)b * SEQ * QKV_N + h * 192;
    const __nv_bfloat16* ql_g = qkvlo + (size_t)b * SEQ * QKV_N + h * 192;
    const __nv_bfloat16* kvsrc[4] = {qh_g + 64, ql_g + 64, qh_g + 128, ql_g + 128};

    #pragma unroll
    for (int i = 0; i < 8; i++) {
        int part = i >> 2;
        int rem = tid + 256 * (i & 3);
        int rw = rem >> 3, cc = rem & 7;
        const __nv_bfloat16* src = (part ? ql_g : qh_g) + (size_t)(q0 + rw) * QKV_N + cc * 8;
        cp16(sb + QOFF + part * 18432 + (uint32_t)rw * RS2 + cc * 16, src);
    }
    CP_COMMIT();

#define LOAD_KV(stg, kk) do {                                                  \
        _Pragma("unroll")                                                      \
        for (int i_ = 0; i_ < 8; i_++) {                                       \
            int sub_ = i_ >> 1;                                                \
            int rem_ = tid + 256 * (i_ & 1);                                   \
            int rw_ = rem_ >> 3, cc_ = rem_ & 7;                               \
            const __nv_bfloat16* src_ =                                        \
                kvsrc[sub_] + (size_t)((kk) + rw_) * QKV_N + cc_ * 8;          \
            cp16(sb + (stg) * STAGE_KV + sub_ * TILE_KV +                      \
                 (uint32_t)rw_ * RS2 + cc_ * 16, src_);                        \
        } } while (0)

    LOAD_KV(0, 0);
    CP_COMMIT();
    CP_WAIT(1);
    __syncthreads();

    uint32_t qhf[4][4], qlf[4][4];
    {
        int ar = 16 * w + (((lane >> 3) & 1) << 3) + (lane & 7);
        int akc = (lane >> 4) << 3;
        #pragma unroll
        for (int ks = 0; ks < 4; ks++) {
            uint32_t ad = sb + QOFF + (uint32_t)ar * RS2 + (uint32_t)(ks * 16 + akc) * 2;
            LDSM4(qhf[ks][0], qhf[ks][1], qhf[ks][2], qhf[ks][3], ad);
            LDSM4(qlf[ks][0], qlf[ks][1], qlf[ks][2], qlf[ks][3], ad + 18432);
        }
    }

    int g = lane >> 2, tg = lane & 3;
    int qr0 = q0 + 16 * w + g, qr1 = qr0 + 8;
    int qmax = q0 + 16 * w + 15;

    float o[8][4];
    #pragma unroll
    for (int nt = 0; nt < 8; nt++)
        #pragma unroll
        for (int i = 0; i < 4; i++) o[nt][i] = 0.f;
    float m0 = -1e30f, m1 = -1e30f, l0 = 0.f, l1 = 0.f;

    int ntile = q0 / 64 + 2;
    int krow = (((lane >> 4)) << 3) + (lane & 7);
    int kkc  = ((lane >> 3) & 1) << 3;
    int vrow_b = (((lane >> 3) & 1) << 3) + (lane & 7);
    int vcol_b = (lane >> 4) << 3;

    for (int t = 0; t < ntile; t++) {
        int k0 = t * 64;
        int buf = t & 1;
        if (t + 1 < ntile) {
            LOAD_KV(buf ^ 1, (t + 1) * 64);
            CP_COMMIT();
            CP_WAIT(1);
        } else {
            CP_WAIT(0);
        }
        __syncthreads();

        if (k0 <= qmax) {
            uint32_t kb = sb + buf * STAGE_KV;
            float s[8][4];
            #pragma unroll
            for (int nt = 0; nt < 8; nt++)
                #pragma unroll
                for (int i = 0; i < 4; i++) s[nt][i] = 0.f;

            #pragma unroll
            for (int ks = 0; ks < 4; ks++) {
                uint32_t khf[8][2], klf[8][2];
                #pragma unroll
                for (int n16 = 0; n16 < 4; n16++) {
                    uint32_t ad = kb + (uint32_t)(n16 * 16 + krow) * RS2
                                     + (uint32_t)(ks * 16 + kkc) * 2;
                    uint32_t t0, t1, t2, t3;
                    LDSM4(t0, t1, t2, t3, ad);
                    khf[n16 * 2][0] = t0; khf[n16 * 2][1] = t1;
                    khf[n16 * 2 + 1][0] = t2; khf[n16 * 2 + 1][1] = t3;
                    LDSM4(t0, t1, t2, t3, ad + TILE_KV);
                    klf[n16 * 2][0] = t0; klf[n16 * 2][1] = t1;
                    klf[n16 * 2 + 1][0] = t2; klf[n16 * 2 + 1][1] = t3;
                }
                #pragma unroll
                for (int nt = 0; nt < 8; nt++) MMA16816(s[nt], qhf[ks], khf[nt]);
                #pragma unroll
                for (int nt = 0; nt < 8; nt++) MMA16816(s[nt], qlf[ks], khf[nt]);
                #pragma unroll
                for (int nt = 0; nt < 8; nt++) MMA16816(s[nt], qhf[ks], klf[nt]);
            }

            #pragma unroll
            for (int nt = 0; nt < 8; nt++)
                #pragma unroll
                for (int i = 0; i < 4; i++) s[nt][i] *= 0.125f;
            if (k0 + 63 > q0 + 16 * w) {
                #pragma unroll
                for (int nt = 0; nt < 8; nt++) {
                    int c = k0 + nt * 8 + 2 * tg;
                    if (c     > qr0) s[nt][0] = -1e30f;
                    if (c + 1 > qr0) s[nt][1] = -1e30f;
                    if (c     > qr1) s[nt][2] = -1e30f;
                    if (c + 1 > qr1) s[nt][3] = -1e30f;
                }
            }

            float rm0 = -1e30f, rm1 = -1e30f;
            #pragma unroll
            for (int nt = 0; nt < 8; nt++) {
                rm0 = fmaxf(rm0, fmaxf(s[nt][0], s[nt][1]));
                rm1 = fmaxf(rm1, fmaxf(s[nt][2], s[nt][3]));
            }
            rm0 = fmaxf(rm0, __shfl_xor_sync(0xffffffffu, rm0, 1));
            rm0 = fmaxf(rm0, __shfl_xor_sync(0xffffffffu, rm0, 2));
            rm1 = fmaxf(rm1, __shfl_xor_sync(0xffffffffu, rm1, 1));
            rm1 = fmaxf(rm1, __shfl_xor_sync(0xffffffffu, rm1, 2));
            float mn0 = fmaxf(m0, rm0), mn1 = fmaxf(m1, rm1);
            float al0 = __expf(m0 - mn0), al1 = __expf(m1 - mn1);
            m0 = mn0; m1 = mn1;
            float rs0 = 0.f, rs1 = 0.f;
            #pragma unroll
            for (int nt = 0; nt < 8; nt++) {
                s[nt][0] = __expf(s[nt][0] - mn0);
                s[nt][1] = __expf(s[nt][1] - mn0);
                s[nt][2] = __expf(s[nt][2] - mn1);
                s[nt][3] = __expf(s[nt][3] - mn1);
                rs0 += s[nt][0] + s[nt][1];
                rs1 += s[nt][2] + s[nt][3];
            }
            rs0 += __shfl_xor_sync(0xffffffffu, rs0, 1);
            rs0 += __shfl_xor_sync(0xffffffffu, rs0, 2);
            rs1 += __shfl_xor_sync(0xffffffffu, rs1, 1);
            rs1 += __shfl_xor_sync(0xffffffffu, rs1, 2);
            l0 = l0 * al0 + rs0;
            l1 = l1 * al1 + rs1;
            #pragma unroll
            for (int nt = 0; nt < 8; nt++) {
                o[nt][0] *= al0; o[nt][1] *= al0;
                o[nt][2] *= al1; o[nt][3] *= al1;
            }

            uint32_t phi[4][4], plo[4][4];
            #pragma unroll
            for (int ks = 0; ks < 4; ks++) {
                phi[ks][0] = packpair(s[2 * ks][0],     s[2 * ks][1],     plo[ks][0]);
                phi[ks][1] = packpair(s[2 * ks][2],     s[2 * ks][3],     plo[ks][1]);
                phi[ks][2] = packpair(s[2 * ks + 1][0], s[2 * ks + 1][1], plo[ks][2]);
                phi[ks][3] = packpair(s[2 * ks + 1][2], s[2 * ks + 1][3], plo[ks][3]);
            }

            uint32_t vb = kb + 2 * TILE_KV;
            #pragma unroll
            for (int ks = 0; ks < 4; ks++) {
                uint32_t vhf[8][2], vlf[8][2];
                #pragma unroll
                for (int n16 = 0; n16 < 4; n16++) {
                    uint32_t ad = vb + (uint32_t)(ks * 16 + vrow_b) * RS2
                                     + (uint32_t)(n16 * 16 + vcol_b) * 2;
                    uint32_t t0, t1, t2, t3;
                    LDSM4T(t0, t1, t2, t3, ad);
                    vhf[n16 * 2][0] = t0; vhf[n16 * 2][1] = t1;
                    vhf[n16 * 2 + 1][0] = t2; vhf[n16 * 2 + 1][1] = t3;
                    LDSM4T(t0, t1, t2, t3, ad + TILE_KV);
                    vlf[n16 * 2][0] = t0; vlf[n16 * 2][1] = t1;
                    vlf[n16 * 2 + 1][0] = t2; vlf[n16 * 2 + 1][1] = t3;
                }
                #pragma unroll
                for (int nt = 0; nt < 8; nt++) MMA16816(o[nt], phi[ks], vhf[nt]);
                #pragma unroll
                for (int nt = 0; nt < 8; nt++) MMA16816(o[nt], plo[ks], vhf[nt]);
                #pragma unroll
                for (int nt = 0; nt < 8; nt++) MMA16816(o[nt], phi[ks], vlf[nt]);
            }
        }
        __syncthreads();
    }
#undef LOAD_KV

    float inv0 = 1.f / l0, inv1 = 1.f / l1;
    size_t base0 = ((size_t)(b * NUM_HEAD + h) * SEQ + qr0) * HEAD_DIM;
    size_t base1 = ((size_t)(b * NUM_HEAD + h) * SEQ + qr1) * HEAD_DIM;
    #pragma unroll
    for (int nt = 0; nt < 8; nt++) {
        int col = nt * 8 + 2 * tg;
        uint32_t lo0, lo1;
        uint32_t hi0 = packpair(o[nt][0] * inv0, o[nt][1] * inv0, lo0);
        uint32_t hi1 = packpair(o[nt][2] * inv1, o[nt][3] * inv1, lo1);
        *(uint32_t*)(ahi + base0 + col) = hi0;
        *(uint32_t*)(alo + base0 + col) = lo0;
        *(uint32_t*)(ahi + base1 + col) = hi1;
        *(uint32_t*)(alo + base1 + col) = lo1;
    }
}

// ---------------------------------------------------------------------------
extern "C" void kernel_launch(void* const* d_in, const int* in_sizes, int n_in,
                              void* d_out, int out_size)
{
    const float* x     = (const float*)d_in[0];
    const float* w_qkv = (const float*)d_in[1];
    const float* b_qkv = (const float*)d_in[2];
    const float* w_out = (const float*)d_in[3];
    const float* b_out = (const float*)d_in[4];
    float* out = (float*)d_out;

    __nv_bfloat16 *qkvhi, *qkvlo, *xhi, *xlo, *wqhi, *wqlo, *wohi, *wolo, *ahi, *alo;
    cudaGetSymbolAddress((void**)&qkvhi, g_qkvhi);
    cudaGetSymbolAddress((void**)&qkvlo, g_qkvlo);
    cudaGetSymbolAddress((void**)&xhi, g_xhi);
    cudaGetSymbolAddress((void**)&xlo, g_xlo);
    cudaGetSymbolAddress((void**)&wqhi, g_wqT_hi);
    cudaGetSymbolAddress((void**)&wqlo, g_wqT_lo);
    cudaGetSymbolAddress((void**)&wohi, g_woT_hi);
    cudaGetSymbolAddress((void**)&wolo, g_woT_lo);
    cudaGetSymbolAddress((void**)&ahi, g_ahi);
    cudaGetSymbolAddress((void**)&alo, g_alo);

    cudaFuncSetAttribute(gemm_mma, cudaFuncAttributeMaxDynamicSharedMemorySize, GEMM_SMEM);
    cudaFuncSetAttribute(flash_attn_mma, cudaFuncAttributeMaxDynamicSharedMemorySize, ATT_SMEM);

    // 0) decompose x and weights
    decomp_kernel<<<MROWS * D_MODEL / 1024, 256>>>(x, xhi, xlo, MROWS * D_MODEL);
    transdecomp_kernel<<<dim3(QKV_N / 32, D_MODEL / 32), dim3(32, 8)>>>(w_qkv, wqhi, wqlo, D_MODEL, QKV_N);
    transdecomp_kernel<<<dim3(D_MODEL / 32, D_MODEL / 32), dim3(32, 8)>>>(w_out, wohi, wolo, D_MODEL, D_MODEL);

    // 1) QKV projection -> hi/lo bf16 directly
    gemm_mma<<<dim3(QKV_N / 128, MROWS / 128), 256, GEMM_SMEM>>>(
        xhi, xlo, wqhi, wqlo, b_qkv, nullptr, qkvhi, qkvlo, MROWS, QKV_N, D_MODEL);

    // 2) causal flash attention (tensor cores) -> ahi/alo
    flash_attn_mma<<<dim3(SEQ / 128, NUM_HEAD, BATCH), 256, ATT_SMEM>>>(
        qkvhi, qkvlo, ahi, alo);

    // 3) output projection -> fp32 out
    gemm_mma<<<dim3(D_MODEL / 128, MROWS / 128), 256, GEMM_SMEM>>>(
        ahi, alo, wohi, wolo, b_out, out, nullptr, nullptr, MROWS, D_MODEL, D_MODEL);
}

// round 7
// speedup vs baseline: 4.0023x; 1.0848x over previous
#include <cuda_runtime.h>
#include <cuda_bf16.h>
#include <stdint.h>
#include <math.h>

#define NUM_HEAD 16
#define D_MODEL 1024
#define HEAD_DIM 64
#define BATCH 2
#define SEQ 2048
#define MROWS (BATCH * SEQ)          // 4096
#define QKV_N (3 * D_MODEL)          // 3072

// ---------------- scratch (device globals: allocation-guard safe) ----------
__device__ __nv_bfloat16 g_qkvhi[(size_t)MROWS * QKV_N];
__device__ __nv_bfloat16 g_qkvlo[(size_t)MROWS * QKV_N];
__device__ __nv_bfloat16 g_xhi[(size_t)MROWS * D_MODEL];
__device__ __nv_bfloat16 g_xlo[(size_t)MROWS * D_MODEL];
__device__ __nv_bfloat16 g_wqT_hi[(size_t)QKV_N * D_MODEL];
__device__ __nv_bfloat16 g_wqT_lo[(size_t)QKV_N * D_MODEL];
__device__ __nv_bfloat16 g_woT_hi[(size_t)D_MODEL * D_MODEL];
__device__ __nv_bfloat16 g_woT_lo[(size_t)D_MODEL * D_MODEL];
__device__ __nv_bfloat16 g_ahi[(size_t)MROWS * D_MODEL];
__device__ __nv_bfloat16 g_alo[(size_t)MROWS * D_MODEL];

// ---------------- PTX helpers ----------------------------------------------
__device__ __forceinline__ uint32_t smem_u32(const void* p) {
    uint32_t a;
    asm("{ .reg .u64 t; cvta.to.shared.u64 t, %1; cvt.u32.u64 %0, t; }" : "=r"(a) : "l"(p));
    return a;
}
__device__ __forceinline__ void cp16(uint32_t dst, const void* src) {
    asm volatile("cp.async.cg.shared.global [%0], [%1], 16;" :: "r"(dst), "l"(src) : "memory");
}
#define CP_COMMIT() asm volatile("cp.async.commit_group;" ::: "memory")
#define CP_WAIT(n)  asm volatile("cp.async.wait_group %0;" :: "n"(n) : "memory")

#define LDSM4(r0, r1, r2, r3, addr) \
    asm volatile("ldmatrix.sync.aligned.m8n8.x4.shared.b16 {%0,%1,%2,%3}, [%4];" \
                 : "=r"(r0), "=r"(r1), "=r"(r2), "=r"(r3) : "r"(addr))
#define LDSM4T(r0, r1, r2, r3, addr) \
    asm volatile("ldmatrix.sync.aligned.m8n8.x4.trans.shared.b16 {%0,%1,%2,%3}, [%4];" \
                 : "=r"(r0), "=r"(r1), "=r"(r2), "=r"(r3) : "r"(addr))

#define MMA16816(d, a, b) \
    asm volatile("mma.sync.aligned.m16n8k16.row.col.f32.bf16.bf16.f32 " \
                 "{%0,%1,%2,%3},{%4,%5,%6,%7},{%8,%9},{%0,%1,%2,%3};" \
                 : "+f"((d)[0]), "+f"((d)[1]), "+f"((d)[2]), "+f"((d)[3]) \
                 : "r"((a)[0]), "r"((a)[1]), "r"((a)[2]), "r"((a)[3]), \
                   "r"((b)[0]), "r"((b)[1]))

__device__ __forceinline__ uint32_t packpair(float x, float y, uint32_t& lo) {
    __nv_bfloat16 hx = __float2bfloat16(x), hy = __float2bfloat16(y);
    __nv_bfloat162 h; h.x = hx; h.y = hy;
    __nv_bfloat162 l;
    l.x = __float2bfloat16(x - __bfloat162float(hx));
    l.y = __float2bfloat16(y - __bfloat162float(hy));
    lo = *(uint32_t*)&l;
    return *(uint32_t*)&h;
}

// ---------------------------------------------------------------------------
__global__ void decomp_kernel(const float* __restrict__ in,
                              __nv_bfloat16* __restrict__ hi,
                              __nv_bfloat16* __restrict__ lo, int n)
{
    int i = (blockIdx.x * blockDim.x + threadIdx.x) * 4;
    if (i >= n) return;
    float4 v = *(const float4*)(in + i);
    uint32_t l0, l1;
    uint32_t h0 = packpair(v.x, v.y, l0);
    uint32_t h1 = packpair(v.z, v.w, l1);
    *(uint32_t*)(hi + i) = h0; *(uint32_t*)(hi + i + 2) = h1;
    *(uint32_t*)(lo + i) = l0; *(uint32_t*)(lo + i + 2) = l1;
}

__global__ void transdecomp_kernel(const float* __restrict__ W,
                                   __nv_bfloat16* __restrict__ Thi,
                                   __nv_bfloat16* __restrict__ Tlo, int K, int N)
{
    __shared__ float tile[32][33];
    int n0 = blockIdx.x * 32, k0 = blockIdx.y * 32;
    #pragma unroll
    for (int i = 0; i < 4; i++)
        tile[threadIdx.y + i * 8][threadIdx.x] =
            W[(size_t)(k0 + threadIdx.y + i * 8) * N + n0 + threadIdx.x];
    __syncthreads();
    #pragma unroll
    for (int i = 0; i < 4; i++) {
        int n = n0 + threadIdx.y + i * 8;
        int k = k0 + threadIdx.x;
        float v = tile[threadIdx.x][threadIdx.y + i * 8];
        __nv_bfloat16 h = __float2bfloat16(v);
        Thi[(size_t)n * K + k] = h;
        Tlo[(size_t)n * K + k] = __float2bfloat16(v - __bfloat162float(h));
    }
}

// ---------------------------------------------------------------------------
// Persistent mma.sync bf16 hi/lo GEMM: C = A[M,K]@B[N,K]^T + bias.
// 128 threads (4 warps 2m x 2n), warp tile 64x64 -> 85B smem per MMA (tensor-
// bound), acc[4][8][4]. 2 CTAs/SM by regs+smem. Cross-tile cp.async prefetch.
// ---------------------------------------------------------------------------
#define RS 80
#define TILE_B 10240          // 128 rows * 80B
#define STAGE_B 40960         // Ahi,Alo,Bhi,Blo
#define GEMM_SMEM 81920       // 2 stages

__global__ __launch_bounds__(128, 2)
void gemm_mma(const __nv_bfloat16* __restrict__ Ahi, const __nv_bfloat16* __restrict__ Alo,
              const __nv_bfloat16* __restrict__ Bhi, const __nv_bfloat16* __restrict__ Blo,
              const float* __restrict__ bias, float* __restrict__ C,
              __nv_bfloat16* __restrict__ Chi, __nv_bfloat16* __restrict__ Clo,
              int M, int N, int K)
{
    extern __shared__ char smem[];
    const uint32_t sb = smem_u32(smem);
    int tid = threadIdx.x;
    int lane = tid & 31, wid = tid >> 5;
    int wm = wid & 1, wn = wid >> 1;       // 2m x 2n warps, 64x64 each

    int NTX = N >> 7;
    int ntiles = (M >> 7) * NTX;

    int m4 = lane >> 3, rin = lane & 7;
    int a_row = wm * 64 + ((m4 & 1) << 3) + rin;
    int a_kc  = (m4 >> 1) << 3;
    int b_row = wn * 64 + ((lane >> 4) << 3) + rin;
    int b_kc  = ((lane >> 3) & 1) << 3;

    const int NC = K / 32;

#define SETP(T, pA, pB, pC, pD, r0_, c0_) do {                               \
        int by_ = (T) / NTX, bx_ = (T) % NTX;                                \
        r0_ = by_ * 128; c0_ = bx_ * 128;                                    \
        pA = Ahi + (size_t)r0_ * K;  pB = Alo + (size_t)r0_ * K;             \
        pC = Bhi + (size_t)c0_ * K;  pD = Blo + (size_t)c0_ * K;             \
    } while (0)

    // 16 cp16 per thread per stage: tile part = i>>2 (512 chunks per tile)
#define LOAD_STAGE(stg, kc, P0, P1, P2, P3) do {                             \
        const __nv_bfloat16* PP_[4] = {P0, P1, P2, P3};                      \
        _Pragma("unroll")                                                    \
        for (int i_ = 0; i_ < 16; i_++) {                                    \
            int tl_ = i_ >> 2;                                               \
            int ci_ = (tid + 128 * i_) & 511;                                \
            int rw_ = ci_ >> 2, cl_ = ci_ & 3;                               \
            cp16(sb + (stg) * STAGE_B + tl_ * TILE_B                         \
                    + (uint32_t)rw_ * RS + cl_ * 16,                         \
                 PP_[tl_] + (size_t)rw_ * K + (kc) + cl_ * 8);               \
        } } while (0)

    int t = blockIdx.x;
    if (t >= ntiles) return;
    const __nv_bfloat16 *pAh, *pAl, *pBh, *pBl;
    int row0, col0;
    SETP(t, pAh, pAl, pBh, pBl, row0, col0);
    LOAD_STAGE(0, 0, pAh, pAl, pBh, pBl);
    CP_COMMIT();

    while (1) {
        float acc[4][8][4];
        #pragma unroll
        for (int i = 0; i < 4; i++)
            #pragma unroll
            for (int j = 0; j < 8; j++)
                #pragma unroll
                for (int r = 0; r < 4; r++) acc[i][j][r] = 0.f;

        int tn = t + gridDim.x;
        const __nv_bfloat16 *nAh = 0, *nAl = 0, *nBh = 0, *nBl = 0;
        int nrow0 = 0, ncol0 = 0;

        for (int c = 0; c < NC; c++) {
            int st = c & 1;
            if (c + 1 < NC) {
                LOAD_STAGE(st ^ 1, (c + 1) * 32, pAh, pAl, pBh, pBl);
                CP_COMMIT();
                CP_WAIT(1);
            } else if (tn < ntiles) {
                SETP(tn, nAh, nAl, nBh, nBl, nrow0, ncol0);
                LOAD_STAGE(st ^ 1, 0, nAh, nAl, nBh, nBl);   // cross-tile prefetch
                CP_COMMIT();
                CP_WAIT(1);
            } else {
                CP_WAIT(0);
            }
            __syncthreads();

            uint32_t aB = sb + st * STAGE_B;
            #pragma unroll
            for (int ks = 0; ks < 2; ks++) {
                uint32_t af[4][4], bhf[8][2], blf[8][2];
                uint32_t adh[4];
                #pragma unroll
                for (int mi = 0; mi < 4; mi++)
                    adh[mi] = aB + (uint32_t)(a_row + mi * 16) * RS
                                 + (uint32_t)(ks * 16 + a_kc) * 2;
                uint32_t bd = aB + 2 * TILE_B + (uint32_t)b_row * RS
                                 + (uint32_t)(ks * 16 + b_kc) * 2;

                #pragma unroll
                for (int mi = 0; mi < 4; mi++)
                    LDSM4(af[mi][0], af[mi][1], af[mi][2], af[mi][3], adh[mi]);
                #pragma unroll
                for (int np = 0; np < 4; np++) {
                    uint32_t t0, t1, t2, t3;
                    LDSM4(t0, t1, t2, t3, bd + (uint32_t)(np * 16) * RS);
                    bhf[np * 2][0] = t0; bhf[np * 2][1] = t1;
                    bhf[np * 2 + 1][0] = t2; bhf[np * 2 + 1][1] = t3;
                }
                #pragma unroll
                for (int np = 0; np < 4; np++) {
                    uint32_t t0, t1, t2, t3;
                    LDSM4(t0, t1, t2, t3, bd + TILE_B + (uint32_t)(np * 16) * RS);
                    blf[np * 2][0] = t0; blf[np * 2][1] = t1;
                    blf[np * 2 + 1][0] = t2; blf[np * 2 + 1][1] = t3;
                }

                // pass 0: Ahi*Bhi
                #pragma unroll
                for (int mi = 0; mi < 4; mi++)
                    #pragma unroll
                    for (int ni = 0; ni < 8; ni++)
                        MMA16816(acc[mi][ni], af[mi], bhf[ni]);
                // pass 1: Ahi*Blo
                #pragma unroll
                for (int mi = 0; mi < 4; mi++)
                    #pragma unroll
                    for (int ni = 0; ni < 8; ni++)
                        MMA16816(acc[mi][ni], af[mi], blf[ni]);
                // load Alo into af, pass 2: Alo*Bhi
                #pragma unroll
                for (int mi = 0; mi < 4; mi++)
                    LDSM4(af[mi][0], af[mi][1], af[mi][2], af[mi][3], adh[mi] + TILE_B);
                #pragma unroll
                for (int mi = 0; mi < 4; mi++)
                    #pragma unroll
                    for (int ni = 0; ni < 8; ni++)
                        MMA16816(acc[mi][ni], af[mi], bhf[ni]);
            }
            __syncthreads();
        }

        // epilogue for tile t
        int g = lane >> 2, tg = lane & 3;
        #pragma unroll
        for (int mi = 0; mi < 4; mi++) {
            int row = row0 + wm * 64 + mi * 16 + g;
            #pragma unroll
            for (int ni = 0; ni < 8; ni++) {
                int col = col0 + wn * 64 + ni * 8 + tg * 2;
                float2 bb = *(const float2*)(bias + col);
                float v0x = acc[mi][ni][0] + bb.x, v0y = acc[mi][ni][1] + bb.y;
                float v1x = acc[mi][ni][2] + bb.x, v1y = acc[mi][ni][3] + bb.y;
                if (Chi) {
                    uint32_t lo0, lo1;
                    uint32_t hi0 = packpair(v0x, v0y, lo0);
                    uint32_t hi1 = packpair(v1x, v1y, lo1);
                    *(uint32_t*)(Chi + (size_t)row * N + col) = hi0;
                    *(uint32_t*)(Clo + (size_t)row * N + col) = lo0;
                    *(uint32_t*)(Chi + (size_t)(row + 8) * N + col) = hi1;
                    *(uint32_t*)(Clo + (size_t)(row + 8) * N + col) = lo1;
                } else {
                    float2 v0; v0.x = v0x; v0.y = v0y;
                    float2 v1; v1.x = v1x; v1.y = v1y;
                    *(float2*)(C + (size_t)row * N + col) = v0;
                    *(float2*)(C + (size_t)(row + 8) * N + col) = v1;
                }
            }
        }

        if (tn >= ntiles) break;
        t = tn;
        pAh = nAh; pAl = nAl; pBh = nBh; pBl = nBl;
        row0 = nrow0; col0 = ncol0;
    }
#undef LOAD_STAGE
#undef SETP
}

// ---------------------------------------------------------------------------
// Flash attention (causal) mma.sync bf16 hi/lo (unchanged from R6).
// ---------------------------------------------------------------------------
#define RS2 144
#define TILE_KV 9216
#define STAGE_KV 36864
#define QOFF 73728
#define ATT_SMEM 110592

__global__ __launch_bounds__(256, 1)
void flash_attn_mma(const __nv_bfloat16* __restrict__ qkvhi,
                    const __nv_bfloat16* __restrict__ qkvlo,
                    __nv_bfloat16* __restrict__ ahi,
                    __nv_bfloat16* __restrict__ alo)
{
    extern __shared__ char smem[];
    const uint32_t sb = smem_u32(smem);
    int tid = threadIdx.x, lane = tid & 31, w = tid >> 5;
    int h = blockIdx.y, b = blockIdx.z;
    int q0 = (int)(gridDim.x - 1 - blockIdx.x) * 128;

    const __nv_bfloat16* qh_g = qkvhi + (size_t)b * SEQ * QKV_N + h * 192;
    const __nv_bfloat16* ql_g = qkvlo + (size_t)b * SEQ * QKV_N + h * 192;
    const __nv_bfloat16* kvsrc[4] = {qh_g + 64, ql_g + 64, qh_g + 128, ql_g + 128};

    #pragma unroll
    for (int i = 0; i < 8; i++) {
        int part = i >> 2;
        int rem = tid + 256 * (i & 3);
        int rw = rem >> 3, cc = rem & 7;
        const __nv_bfloat16* src = (part ? ql_g : qh_g) + (size_t)(q0 + rw) * QKV_N + cc * 8;
        cp16(sb + QOFF + part * 18432 + (uint32_t)rw * RS2 + cc * 16, src);
    }
    CP_COMMIT();

#define LOAD_KV(stg, kk) do {                                                  \
        _Pragma("unroll")                                                      \
        for (int i_ = 0; i_ < 8; i_++) {                                       \
            int sub_ = i_ >> 1;                                                \
            int rem_ = tid + 256 * (i_ & 1);                                   \
            int rw_ = rem_ >> 3, cc_ = rem_ & 7;                               \
            const __nv_bfloat16* src_ =                                        \
                kvsrc[sub_] + (size_t)((kk) + rw_) * QKV_N + cc_ * 8;          \
            cp16(sb + (stg) * STAGE_KV + sub_ * TILE_KV +                      \
                 (uint32_t)rw_ * RS2 + cc_ * 16, src_);                        \
        } } while (0)

    LOAD_KV(0, 0);
    CP_COMMIT();
    CP_WAIT(1);
    __syncthreads();

    uint32_t qhf[4][4], qlf[4][4];
    {
        int ar = 16 * w + (((lane >> 3) & 1) << 3) + (lane & 7);
        int akc = (lane >> 4) << 3;
        #pragma unroll
        for (int ks = 0; ks < 4; ks++) {
            uint32_t ad = sb + QOFF + (uint32_t)ar * RS2 + (uint32_t)(ks * 16 + akc) * 2;
            LDSM4(qhf[ks][0], qhf[ks][1], qhf[ks][2], qhf[ks][3], ad);
            LDSM4(qlf[ks][0], qlf[ks][1], qlf[ks][2], qlf[ks][3], ad + 18432);
        }
    }

    int g = lane >> 2, tg = lane & 3;
    int qr0 = q0 + 16 * w + g, qr1 = qr0 + 8;
    int qmax = q0 + 16 * w + 15;

    float o[8][4];
    #pragma unroll
    for (int nt = 0; nt < 8; nt++)
        #pragma unroll
        for (int i = 0; i < 4; i++) o[nt][i] = 0.f;
    float m0 = -1e30f, m1 = -1e30f, l0 = 0.f, l1 = 0.f;

    int ntile = q0 / 64 + 2;
    int krow = (((lane >> 4)) << 3) + (lane & 7);
    int kkc  = ((lane >> 3) & 1) << 3;
    int vrow_b = (((lane >> 3) & 1) << 3) + (lane & 7);
    int vcol_b = (lane >> 4) << 3;

    for (int t = 0; t < ntile; t++) {
        int k0 = t * 64;
        int buf = t & 1;
        if (t + 1 < ntile) {
            LOAD_KV(buf ^ 1, (t + 1) * 64);
            CP_COMMIT();
            CP_WAIT(1);
        } else {
            CP_WAIT(0);
        }
        __syncthreads();

        if (k0 <= qmax) {
            uint32_t kb = sb + buf * STAGE_KV;
            float s[8][4];
            #pragma unroll
            for (int nt = 0; nt < 8; nt++)
                #pragma unroll
                for (int i = 0; i < 4; i++) s[nt][i] = 0.f;

            #pragma unroll
            for (int ks = 0; ks < 4; ks++) {
                uint32_t khf[8][2], klf[8][2];
                #pragma unroll
                for (int n16 = 0; n16 < 4; n16++) {
                    uint32_t ad = kb + (uint32_t)(n16 * 16 + krow) * RS2
                                     + (uint32_t)(ks * 16 + kkc) * 2;
                    uint32_t t0, t1, t2, t3;
                    LDSM4(t0, t1, t2, t3, ad);
                    khf[n16 * 2][0] = t0; khf[n16 * 2][1] = t1;
                    khf[n16 * 2 + 1][0] = t2; khf[n16 * 2 + 1][1] = t3;
                    LDSM4(t0, t1, t2, t3, ad + TILE_KV);
                    klf[n16 * 2][0] = t0; klf[n16 * 2][1] = t1;
                    klf[n16 * 2 + 1][0] = t2; klf[n16 * 2 + 1][1] = t3;
                }
                #pragma unroll
                for (int nt = 0; nt < 8; nt++) MMA16816(s[nt], qhf[ks], khf[nt]);
                #pragma unroll
                for (int nt = 0; nt < 8; nt++) MMA16816(s[nt], qlf[ks], khf[nt]);
                #pragma unroll
                for (int nt = 0; nt < 8; nt++) MMA16816(s[nt], qhf[ks], klf[nt]);
            }

            #pragma unroll
            for (int nt = 0; nt < 8; nt++)
                #pragma unroll
                for (int i = 0; i < 4; i++) s[nt][i] *= 0.125f;
            if (k0 + 63 > q0 + 16 * w) {
                #pragma unroll
                for (int nt = 0; nt < 8; nt++) {
                    int c = k0 + nt * 8 + 2 * tg;
                    if (c     > qr0) s[nt][0] = -1e30f;
                    if (c + 1 > qr0) s[nt][1] = -1e30f;
                    if (c     > qr1) s[nt][2] = -1e30f;
                    if (c + 1 > qr1) s[nt][3] = -1e30f;
                }
            }

            float rm0 = -1e30f, rm1 = -1e30f;
            #pragma unroll
            for (int nt = 0; nt < 8; nt++) {
                rm0 = fmaxf(rm0, fmaxf(s[nt][0], s[nt][1]));
                rm1 = fmaxf(rm1, fmaxf(s[nt][2], s[nt][3]));
            }
            rm0 = fmaxf(rm0, __shfl_xor_sync(0xffffffffu, rm0, 1));
            rm0 = fmaxf(rm0, __shfl_xor_sync(0xffffffffu, rm0, 2));
            rm1 = fmaxf(rm1, __shfl_xor_sync(0xffffffffu, rm1, 1));
            rm1 = fmaxf(rm1, __shfl_xor_sync(0xffffffffu, rm1, 2));
            float mn0 = fmaxf(m0, rm0), mn1 = fmaxf(m1, rm1);
            float al0 = __expf(m0 - mn0), al1 = __expf(m1 - mn1);
            m0 = mn0; m1 = mn1;
            float rs0 = 0.f, rs1 = 0.f;
            #pragma unroll
            for (int nt = 0; nt < 8; nt++) {
                s[nt][0] = __expf(s[nt][0] - mn0);
                s[nt][1] = __expf(s[nt][1] - mn0);
                s[nt][2] = __expf(s[nt][2] - mn1);
                s[nt][3] = __expf(s[nt][3] - mn1);
                rs0 += s[nt][0] + s[nt][1];
                rs1 += s[nt][2] + s[nt][3];
            }
            rs0 += __shfl_xor_sync(0xffffffffu, rs0, 1);
            rs0 += __shfl_xor_sync(0xffffffffu, rs0, 2);
            rs1 += __shfl_xor_sync(0xffffffffu, rs1, 1);
            rs1 += __shfl_xor_sync(0xffffffffu, rs1, 2);
            l0 = l0 * al0 + rs0;
            l1 = l1 * al1 + rs1;
            #pragma unroll
            for (int nt = 0; nt < 8; nt++) {
                o[nt][0] *= al0; o[nt][1] *= al0;
                o[nt][2] *= al1; o[nt][3] *= al1;
            }

            uint32_t phi[4][4], plo[4][4];
            #pragma unroll
            for (int ks = 0; ks < 4; ks++) {
                phi[ks][0] = packpair(s[2 * ks][0],     s[2 * ks][1],     plo[ks][0]);
                phi[ks][1] = packpair(s[2 * ks][2],     s[2 * ks][3],     plo[ks][1]);
                phi[ks][2] = packpair(s[2 * ks + 1][0], s[2 * ks + 1][1], plo[ks][2]);
                phi[ks][3] = packpair(s[2 * ks + 1][2], s[2 * ks + 1][3], plo[ks][3]);
            }

            uint32_t vb = kb + 2 * TILE_KV;
            #pragma unroll
            for (int ks = 0; ks < 4; ks++) {
                uint32_t vhf[8][2], vlf[8][2];
                #pragma unroll
                for (int n16 = 0; n16 < 4; n16++) {
                    uint32_t ad = vb + (uint32_t)(ks * 16 + vrow_b) * RS2
                                     + (uint32_t)(n16 * 16 + vcol_b) * 2;
                    uint32_t t0, t1, t2, t3;
                    LDSM4T(t0, t1, t2, t3, ad);
                    vhf[n16 * 2][0] = t0; vhf[n16 * 2][1] = t1;
                    vhf[n16 * 2 + 1][0] = t2; vhf[n16 * 2 + 1][1] = t3;
                    LDSM4T(t0, t1, t2, t3, ad + TILE_KV);
                    vlf[n16 * 2][0] = t0; vlf[n16 * 2][1] = t1;
                    vlf[n16 * 2 + 1][0] = t2; vlf[n16 * 2 + 1][1] = t3;
                }
                #pragma unroll
                for (int nt = 0; nt < 8; nt++) MMA16816(o[nt], phi[ks], vhf[nt]);
                #pragma unroll
                for (int nt = 0; nt < 8; nt++) MMA16816(o[nt], plo[ks], vhf[nt]);
                #pragma unroll
                for (int nt = 0; nt < 8; nt++) MMA16816(o[nt], phi[ks], vlf[nt]);
            }
        }
        __syncthreads();
    }
#undef LOAD_KV

    float inv0 = 1.f / l0, inv1 = 1.f / l1;
    size_t base0 = ((size_t)(b * NUM_HEAD + h) * SEQ + qr0) * HEAD_DIM;
    size_t base1 = ((size_t)(b * NUM_HEAD + h) * SEQ + qr1) * HEAD_DIM;
    #pragma unroll
    for (int nt = 0; nt < 8; nt++) {
        int col = nt * 8 + 2 * tg;
        uint32_t lo0, lo1;
        uint32_t hi0 = packpair(o[nt][0] * inv0, o[nt][1] * inv0, lo0);
        uint32_t hi1 = packpair(o[nt][2] * inv1, o[nt][3] * inv1, lo1);
        *(uint32_t*)(ahi + base0 + col) = hi0;
        *(uint32_t*)(alo + base0 + col) = lo0;
        *(uint32_t*)(ahi + base1 + col) = hi1;
        *(uint32_t*)(alo + base1 + col) = lo1;
    }
}

// ---------------------------------------------------------------------------
extern "C" void kernel_launch(void* const* d_in, const int* in_sizes, int n_in,
                              void* d_out, int out_size)
{
    const float* x     = (const float*)d_in[0];
    const float* w_qkv = (const float*)d_in[1];
    const float* b_qkv = (const float*)d_in[2];
    const float* w_out = (const float*)d_in[3];
    const float* b_out = (const float*)d_in[4];
    float* out = (float*)d_out;

    __nv_bfloat16 *qkvhi, *qkvlo, *xhi, *xlo, *wqhi, *wqlo, *wohi, *wolo, *ahi, *alo;
    cudaGetSymbolAddress((void**)&qkvhi, g_qkvhi);
    cudaGetSymbolAddress((void**)&qkvlo, g_qkvlo);
    cudaGetSymbolAddress((void**)&xhi, g_xhi);
    cudaGetSymbolAddress((void**)&xlo, g_xlo);
    cudaGetSymbolAddress((void**)&wqhi, g_wqT_hi);
    cudaGetSymbolAddress((void**)&wqlo, g_wqT_lo);
    cudaGetSymbolAddress((void**)&wohi, g_woT_hi);
    cudaGetSymbolAddress((void**)&wolo, g_woT_lo);
    cudaGetSymbolAddress((void**)&ahi, g_ahi);
    cudaGetSymbolAddress((void**)&alo, g_alo);

    cudaFuncSetAttribute(gemm_mma, cudaFuncAttributeMaxDynamicSharedMemorySize, GEMM_SMEM);
    cudaFuncSetAttribute(flash_attn_mma, cudaFuncAttributeMaxDynamicSharedMemorySize, ATT_SMEM);

    // 0) decompose x and weights
    decomp_kernel<<<MROWS * D_MODEL / 1024, 256>>>(x, xhi, xlo, MROWS * D_MODEL);
    transdecomp_kernel<<<dim3(QKV_N / 32, D_MODEL / 32), dim3(32, 8)>>>(w_qkv, wqhi, wqlo, D_MODEL, QKV_N);
    transdecomp_kernel<<<dim3(D_MODEL / 32, D_MODEL / 32), dim3(32, 8)>>>(w_out, wohi, wolo, D_MODEL, D_MODEL);

    // 1) QKV projection -> hi/lo bf16 (persistent grid: 2 CTAs x 148 SMs)
    {
        int ntiles = (MROWS / 128) * (QKV_N / 128);   // 768
        int grid = ntiles < 296 ? ntiles : 296;
        gemm_mma<<<grid, 128, GEMM_SMEM>>>(
            xhi, xlo, wqhi, wqlo, b_qkv, nullptr, qkvhi, qkvlo, MROWS, QKV_N, D_MODEL);
    }

    // 2) causal flash attention (tensor cores) -> ahi/alo
    flash_attn_mma<<<dim3(SEQ / 128, NUM_HEAD, BATCH), 256, ATT_SMEM>>>(
        qkvhi, qkvlo, ahi, alo);

    // 3) output projection -> fp32 out
    {
        int ntiles = (MROWS / 128) * (D_MODEL / 128);  // 256
        int grid = ntiles < 296 ? ntiles : 296;
        gemm_mma<<<grid, 128, GEMM_SMEM>>>(
            ahi, alo, wohi, wolo, b_out, out, nullptr, nullptr, MROWS, D_MODEL, D_MODEL);
    }
}